// round 2
// baseline (speedup 1.0000x reference)
#include <cuda_runtime.h>

#define NUQ 500000
#define NIQ 100000
#define FQ  300
#define DQ  64
#define EQ  2000000
#define ELQ 1000000

// ---------------- scratch (device globals; no allocations allowed) -------------
__device__ __align__(16) float g_xu  [NUQ * DQ];   // user input features (gathered)
__device__ __align__(16) float g_xi  [NIQ * DQ];   // item input features (linear)
__device__ __align__(16) float g_aggu[NUQ * DQ];   // scatter accumulator (users)
__device__ __align__(16) float g_aggi[NIQ * DQ];   // scatter accumulator (items)
__device__ __align__(16) float g_hu  [NUQ * DQ];   // layer-1 user out (relu)
__device__ __align__(16) float g_hi  [NIQ * DQ];   // layer-1 item out (relu)
__device__ __align__(16) float g_hu2 [NUQ * DQ];   // layer-2 user out
__device__ __align__(16) float g_hi2 [NIQ * DQ];   // layer-2 item out
__device__ __align__(16) float g_degu[NUQ];
__device__ __align__(16) float g_degi[NIQ];

// ---------------- zero kernels -------------------------------------------------
__global__ void k_zero_deg() {
    int i = blockIdx.x * blockDim.x + threadIdx.x;
    if (i < NUQ) g_degu[i] = 0.f;
    else if (i < NUQ + NIQ) g_degi[i - NUQ] = 0.f;
}

__global__ void k_zero_agg() {
    // (NUQ+NIQ)*16 float4 = 9.6M, launched exactly
    int i = blockIdx.x * blockDim.x + threadIdx.x;
    float4 z = make_float4(0.f, 0.f, 0.f, 0.f);
    if (i < NUQ * 16) ((float4*)g_aggu)[i] = z;
    else              ((float4*)g_aggi)[i - NUQ * 16] = z;
}

// ---------------- degree counts ------------------------------------------------
__global__ void k_degree(const int* __restrict__ src, const int* __restrict__ dst) {
    int i = blockIdx.x * blockDim.x + threadIdx.x;
    if (i < EQ) {
        atomicAdd(&g_degu[src[i]], 1.f);
        atomicAdd(&g_degi[dst[i]], 1.f);
    }
}

// ---------------- user embedding gather ---------------------------------------
__global__ void k_gather(const float4* __restrict__ emb, const int* __restrict__ nid) {
    int i = blockIdx.x * blockDim.x + threadIdx.x;   // exactly NUQ*16
    int row = i >> 4;
    int id = nid[row];
    ((float4*)g_xu)[i] = emb[(size_t)id * 16 + (i & 15)];
}

// ---------------- item linear: xi = item_x @ W + b -----------------------------
// block = 128 threads; 2 rows per iteration, 16 iterations -> 32 rows per block.
// W (300x64) staged in dynamic smem.
__global__ __launch_bounds__(128) void k_item_linear(
    const float* __restrict__ X, const float* __restrict__ W, const float* __restrict__ bias)
{
    extern __shared__ float sm[];
    float* sW = sm;             // 300*64 = 19200 floats
    float* sx = sm + 19200;     // 2 rows, pitch 304

    const int tid = threadIdx.x;
    for (int i = tid; i < FQ * DQ; i += 128) sW[i] = W[i];
    const float bb = bias[tid & 63];
    const int half = tid >> 6;        // 0/1 -> row within pair
    const int col  = tid & 63;
    const int row0 = blockIdx.x * 32;

    for (int it = 0; it < 16; ++it) {
        __syncthreads();
        int r0 = row0 + it * 2;
        for (int i = tid; i < 2 * FQ; i += 128) {
            int rr = i / FQ, cc = i - rr * FQ;
            int gr = r0 + rr;
            sx[rr * 304 + cc] = (gr < NIQ) ? X[(size_t)gr * FQ + cc] : 0.f;
        }
        __syncthreads();
        int gr = r0 + half;
        const float* xr = sx + half * 304;
        float a0 = bb, a1 = 0.f, a2 = 0.f, a3 = 0.f;
        #pragma unroll 5
        for (int f = 0; f < FQ; f += 4) {
            float4 xv = *(const float4*)(xr + f);
            a0 += xv.x * sW[(f + 0) * 64 + col];
            a1 += xv.y * sW[(f + 1) * 64 + col];
            a2 += xv.z * sW[(f + 2) * 64 + col];
            a3 += xv.w * sW[(f + 3) * 64 + col];
        }
        if (gr < NIQ) g_xi[(size_t)gr * 64 + col] = (a0 + a1) + (a2 + a3);
    }
}

// ---------------- fused bidirectional scatter ----------------------------------
// 16 threads per edge. Each thread: one float4 of the user row -> item accum,
// one float4 of the item row -> user accum. Exactly EQ*16 threads.
__global__ void k_scatter(const float4* __restrict__ utab, const float4* __restrict__ itab,
                          const int* __restrict__ src, const int* __restrict__ dst,
                          float* __restrict__ aggu, float* __restrict__ aggi)
{
    int t = blockIdx.x * blockDim.x + threadIdx.x;   // 32M exactly
    int e = t >> 4;
    int q = t & 15;
    int lane = threadIdx.x & 31;

    int s = 0, d = 0;
    if ((lane & 15) == 0) { s = src[e]; d = dst[e]; }
    s = __shfl_sync(0xffffffffu, s, lane & 16);
    d = __shfl_sync(0xffffffffu, d, lane & 16);

    float4 uv = utab[(size_t)s * 16 + q];
    float* ai = aggi + (size_t)d * 64 + q * 4;
    atomicAdd(ai + 0, uv.x);
    atomicAdd(ai + 1, uv.y);
    atomicAdd(ai + 2, uv.z);
    atomicAdd(ai + 3, uv.w);

    float4 iv = itab[(size_t)d * 16 + q];
    float* au = aggu + (size_t)s * 64 + q * 4;
    atomicAdd(au + 0, iv.x);
    atomicAdd(au + 1, iv.y);
    atomicAdd(au + 2, iv.z);
    atomicAdd(au + 3, iv.w);
}

// ---------------- fused dual GEMM combine --------------------------------------
// out = act( (agg * 1/max(deg,1)) @ Wl + x @ Wr + b )
// block = 128 threads (16 tx x 8 ty), tile = 64 rows x 64 cols,
// micro-tile 8 rows x 4 cols per thread. Inputs staged transposed (pitch 68).
template <bool RELU>
__global__ __launch_bounds__(128) void k_combine(
    int n, const float* __restrict__ agg, const float* __restrict__ deg,
    const float* __restrict__ x, const float* __restrict__ Wl,
    const float* __restrict__ Wr, const float* __restrict__ b,
    float* __restrict__ out)
{
    extern __shared__ float sm[];
    float* sWl = sm;                 // 4096
    float* sWr = sm + 4096;          // 4096
    float* sB  = sm + 8192;          // 64
    float* saT = sm + 8192 + 64;     // 64 x 68
    float* sxT = saT + 64 * 68;      // 64 x 68

    const int tid = threadIdx.x;
    const int tx = tid & 15;
    const int ty = tid >> 4;
    const int row0 = blockIdx.x * 64;

    for (int i = tid; i < 4096; i += 128) { sWl[i] = Wl[i]; sWr[i] = Wr[i]; }
    if (tid < 64) sB[tid] = b[tid];

    // stage 64x64 tiles of agg (pre-scaled) and x, transposed
    for (int i = tid; i < 1024; i += 128) {
        int r = i >> 4, c4 = i & 15;
        int grow = row0 + r;
        float4 av, xv;
        float rd = 1.f;
        if (grow < n) {
            av = ((const float4*)agg)[(size_t)grow * 16 + c4];
            xv = ((const float4*)x)[(size_t)grow * 16 + c4];
            rd = 1.f / fmaxf(deg[grow], 1.f);
        } else {
            av = make_float4(0.f, 0.f, 0.f, 0.f);
            xv = av;
        }
        int c = c4 * 4;
        saT[(c + 0) * 68 + r] = av.x * rd;
        saT[(c + 1) * 68 + r] = av.y * rd;
        saT[(c + 2) * 68 + r] = av.z * rd;
        saT[(c + 3) * 68 + r] = av.w * rd;
        sxT[(c + 0) * 68 + r] = xv.x;
        sxT[(c + 1) * 68 + r] = xv.y;
        sxT[(c + 2) * 68 + r] = xv.z;
        sxT[(c + 3) * 68 + r] = xv.w;
    }
    __syncthreads();

    float acc[8][4];
    #pragma unroll
    for (int r = 0; r < 8; ++r)
        #pragma unroll
        for (int c = 0; c < 4; ++c)
            acc[r][c] = (r == 0) ? sB[tx * 4 + c] : 0.f;   // bias added once (row r=0 slot per-col; fix below)

    // NOTE: bias must be added to EVERY row; re-init properly:
    #pragma unroll
    for (int r = 0; r < 8; ++r)
        #pragma unroll
        for (int c = 0; c < 4; ++c)
            acc[r][c] = sB[tx * 4 + c];

    #pragma unroll 4
    for (int k = 0; k < 64; ++k) {
        float4 a0 = *(const float4*)&saT[k * 68 + ty * 8];
        float4 a1 = *(const float4*)&saT[k * 68 + ty * 8 + 4];
        float4 wl = *(const float4*)&sWl[k * 64 + tx * 4];
        float4 x0 = *(const float4*)&sxT[k * 68 + ty * 8];
        float4 x1 = *(const float4*)&sxT[k * 68 + ty * 8 + 4];
        float4 wr = *(const float4*)&sWr[k * 64 + tx * 4];

        float ar[8] = {a0.x, a0.y, a0.z, a0.w, a1.x, a1.y, a1.z, a1.w};
        float xr[8] = {x0.x, x0.y, x0.z, x0.w, x1.x, x1.y, x1.z, x1.w};
        float wlc[4] = {wl.x, wl.y, wl.z, wl.w};
        float wrc[4] = {wr.x, wr.y, wr.z, wr.w};
        #pragma unroll
        for (int r = 0; r < 8; ++r)
            #pragma unroll
            for (int c = 0; c < 4; ++c)
                acc[r][c] += ar[r] * wlc[c] + xr[r] * wrc[c];
    }

    #pragma unroll
    for (int r = 0; r < 8; ++r) {
        int grow = row0 + ty * 8 + r;
        if (grow < n) {
            float4 o;
            o.x = acc[r][0]; o.y = acc[r][1]; o.z = acc[r][2]; o.w = acc[r][3];
            if (RELU) {
                o.x = fmaxf(o.x, 0.f); o.y = fmaxf(o.y, 0.f);
                o.z = fmaxf(o.z, 0.f); o.w = fmaxf(o.w, 0.f);
            }
            ((float4*)out)[(size_t)grow * 16 + tx] = o;
        }
    }
}

// ---------------- dot-product predictor ----------------------------------------
// 8 lanes per edge, each lane 8 floats (2 float4) per side, shfl tree reduce.
__global__ void k_predict(const float* __restrict__ hu, const float* __restrict__ hi,
                          const int* __restrict__ ls, const int* __restrict__ ld,
                          float* __restrict__ out)
{
    int t = blockIdx.x * blockDim.x + threadIdx.x;   // ELQ*8 exactly
    int e = t >> 3;
    int q = t & 7;
    int s = ls[e];
    int d = ld[e];
    const float4* hu4 = (const float4*)hu;
    const float4* hi4 = (const float4*)hi;
    float4 a0 = hu4[(size_t)s * 16 + q * 2];
    float4 a1 = hu4[(size_t)s * 16 + q * 2 + 1];
    float4 b0 = hi4[(size_t)d * 16 + q * 2];
    float4 b1 = hi4[(size_t)d * 16 + q * 2 + 1];
    float p = a0.x * b0.x + a0.y * b0.y + a0.z * b0.z + a0.w * b0.w
            + a1.x * b1.x + a1.y * b1.y + a1.z * b1.z + a1.w * b1.w;
    p += __shfl_down_sync(0xffffffffu, p, 4);
    p += __shfl_down_sync(0xffffffffu, p, 2);
    p += __shfl_down_sync(0xffffffffu, p, 1);
    if (q == 0) out[e] = p;
}

// ---------------- host orchestration -------------------------------------------
extern "C" void kernel_launch(void* const* d_in, const int* in_sizes, int n_in,
                              void* d_out, int out_size)
{
    const float* user_emb   = (const float*)d_in[0];
    const float* item_x     = (const float*)d_in[1];
    const float* item_lin_w = (const float*)d_in[2];
    const float* item_lin_b = (const float*)d_in[3];
    const float* Wl1_ui = (const float*)d_in[4];
    const float* Wr1_ui = (const float*)d_in[5];
    const float* b1_ui  = (const float*)d_in[6];
    const float* Wl1_iu = (const float*)d_in[7];
    const float* Wr1_iu = (const float*)d_in[8];
    const float* b1_iu  = (const float*)d_in[9];
    const float* Wl2_ui = (const float*)d_in[10];
    const float* Wr2_ui = (const float*)d_in[11];
    const float* b2_ui  = (const float*)d_in[12];
    const float* Wl2_iu = (const float*)d_in[13];
    const float* Wr2_iu = (const float*)d_in[14];
    const float* b2_iu  = (const float*)d_in[15];
    const int* user_node_id = (const int*)d_in[16];
    const int* esrc = (const int*)d_in[17];
    const int* edst = (const int*)d_in[18];
    const int* lsrc = (const int*)d_in[19];
    const int* ldst = (const int*)d_in[20];
    float* out = (float*)d_out;

    float *p_xu, *p_xi, *p_aggu, *p_aggi, *p_hu, *p_hi, *p_hu2, *p_hi2, *p_degu, *p_degi;
    cudaGetSymbolAddress((void**)&p_xu,   g_xu);
    cudaGetSymbolAddress((void**)&p_xi,   g_xi);
    cudaGetSymbolAddress((void**)&p_aggu, g_aggu);
    cudaGetSymbolAddress((void**)&p_aggi, g_aggi);
    cudaGetSymbolAddress((void**)&p_hu,   g_hu);
    cudaGetSymbolAddress((void**)&p_hi,   g_hi);
    cudaGetSymbolAddress((void**)&p_hu2,  g_hu2);
    cudaGetSymbolAddress((void**)&p_hi2,  g_hi2);
    cudaGetSymbolAddress((void**)&p_degu, g_degu);
    cudaGetSymbolAddress((void**)&p_degi, g_degi);

    const int SMEM_LIN = (19200 + 2 * 304) * 4;            // 79232 B
    const int SMEM_CMB = (8192 + 64 + 2 * 64 * 68) * 4;    // 67840 B
    cudaFuncSetAttribute(k_item_linear,   cudaFuncAttributeMaxDynamicSharedMemorySize, SMEM_LIN);
    cudaFuncSetAttribute(k_combine<true>, cudaFuncAttributeMaxDynamicSharedMemorySize, SMEM_CMB);
    cudaFuncSetAttribute(k_combine<false>,cudaFuncAttributeMaxDynamicSharedMemorySize, SMEM_CMB);

    // degrees (shared by both layers)
    k_zero_deg<<<(NUQ + NIQ + 255) / 256, 256>>>();
    k_degree<<<(EQ + 255) / 256, 256>>>(esrc, edst);

    // input features
    k_gather<<<NUQ * 16 / 256, 256>>>((const float4*)user_emb, user_node_id);
    k_item_linear<<<(NIQ + 31) / 32, 128, SMEM_LIN>>>(item_x, item_lin_w, item_lin_b);

    // ---- layer 1 ----
    k_zero_agg<<<(NUQ + NIQ) * 16 / 256, 256>>>();
    k_scatter<<<EQ * 16 / 256, 256>>>((const float4*)p_xu, (const float4*)p_xi,
                                      esrc, edst, p_aggu, p_aggi);
    k_combine<true><<<(NIQ + 63) / 64, 128, SMEM_CMB>>>(NIQ, p_aggi, p_degi, p_xi,
                                                        Wl1_ui, Wr1_ui, b1_ui, p_hi);
    k_combine<true><<<(NUQ + 63) / 64, 128, SMEM_CMB>>>(NUQ, p_aggu, p_degu, p_xu,
                                                        Wl1_iu, Wr1_iu, b1_iu, p_hu);

    // ---- layer 2 ----
    k_zero_agg<<<(NUQ + NIQ) * 16 / 256, 256>>>();
    k_scatter<<<EQ * 16 / 256, 256>>>((const float4*)p_hu, (const float4*)p_hi,
                                      esrc, edst, p_aggu, p_aggi);
    k_combine<false><<<(NIQ + 63) / 64, 128, SMEM_CMB>>>(NIQ, p_aggi, p_degi, p_hi,
                                                         Wl2_ui, Wr2_ui, b2_ui, p_hi2);
    k_combine<false><<<(NUQ + 63) / 64, 128, SMEM_CMB>>>(NUQ, p_aggu, p_degu, p_hu,
                                                         Wl2_iu, Wr2_iu, b2_iu, p_hu2);

    // ---- predictor ----
    k_predict<<<ELQ * 8 / 256, 256>>>(p_hu2, p_hi2, lsrc, ldst, out);
}

// round 3
// speedup vs baseline: 1.7928x; 1.7928x over previous
#include <cuda_runtime.h>

#define NUQ 500000
#define NIQ 100000
#define FQ  300
#define DQ  64
#define EQ  2000000
#define ELQ 1000000

// ---------------- scratch (device globals; no allocations allowed) -------------
__device__ __align__(16) float g_xu  [NUQ * DQ];   // user input features (gathered)
__device__ __align__(16) float g_xi  [NIQ * DQ];   // item input features (linear)
__device__ __align__(16) float g_aggu[NUQ * DQ];   // scatter accumulator (users)
__device__ __align__(16) float g_aggi[NIQ * DQ];   // scatter accumulator (items)
__device__ __align__(16) float g_hu  [NUQ * DQ];   // layer-1 user out (relu)
__device__ __align__(16) float g_hi  [NIQ * DQ];   // layer-1 item out (relu)
__device__ __align__(16) float g_hu2 [NUQ * DQ];   // layer-2 user out
__device__ __align__(16) float g_hi2 [NIQ * DQ];   // layer-2 item out
__device__ __align__(16) float g_degu[NUQ];
__device__ __align__(16) float g_degi[NIQ];

// ---------------- degree counts ------------------------------------------------
__global__ void k_degree(const int* __restrict__ src, const int* __restrict__ dst) {
    int i = blockIdx.x * blockDim.x + threadIdx.x;
    if (i < EQ) {
        atomicAdd(&g_degu[src[i]], 1.f);
        atomicAdd(&g_degi[dst[i]], 1.f);
    }
}

// ---------------- user embedding gather ---------------------------------------
__global__ void k_gather(const float4* __restrict__ emb, const int* __restrict__ nid) {
    int i = blockIdx.x * blockDim.x + threadIdx.x;   // exactly NUQ*16
    int row = i >> 4;
    int id = nid[row];
    ((float4*)g_xu)[i] = emb[(size_t)id * 16 + (i & 15)];
}

// ---------------- item linear GEMM: xi = item_x @ W + b ------------------------
// Proper tiled GEMM. Tile: 64 rows x 64 cols. Block: 128 threads (16 tx x 8 ty),
// micro-tile 8 rows x 4 cols. K=300 in 5 chunks of 60 staged in smem.
__global__ __launch_bounds__(128) void k_item_gemm(
    const float* __restrict__ X, const float* __restrict__ W, const float* __restrict__ bias)
{
    __shared__ float sW [60 * 64];        // W chunk [k][c]
    __shared__ float sXT[60 * 68];        // X chunk transposed [k][r], pitch 68

    const int tid = threadIdx.x;
    const int tx  = tid & 15;             // 4 output cols: tx*4..
    const int ty  = tid >> 4;             // 8 output rows: ty*8..
    const int row0 = blockIdx.x * 64;

    const float4 bv = ((const float4*)bias)[tx];
    float acc[8][4];
    #pragma unroll
    for (int r = 0; r < 8; ++r) {
        acc[r][0] = bv.x; acc[r][1] = bv.y; acc[r][2] = bv.z; acc[r][3] = bv.w;
    }

    for (int k0 = 0; k0 < FQ; k0 += 60) {
        __syncthreads();
        // W chunk: 60 x 64 floats = 960 float4, contiguous
        const float4* Wg = (const float4*)(W + k0 * 64);
        for (int i = tid; i < 960; i += 128)
            ((float4*)sW)[i] = Wg[i];
        // X chunk: 64 rows x 15 float4, transposed into sXT[k][r]
        for (int i = tid; i < 960; i += 128) {
            int r  = i / 15;
            int c4 = i - r * 15;
            int grow = row0 + r;
            float4 v = make_float4(0.f, 0.f, 0.f, 0.f);
            if (grow < NIQ)
                v = *(const float4*)(X + (size_t)grow * FQ + k0 + c4 * 4);
            int k = c4 * 4;
            sXT[(k + 0) * 68 + r] = v.x;
            sXT[(k + 1) * 68 + r] = v.y;
            sXT[(k + 2) * 68 + r] = v.z;
            sXT[(k + 3) * 68 + r] = v.w;
        }
        __syncthreads();

        #pragma unroll 6
        for (int k = 0; k < 60; ++k) {
            float4 a0 = *(const float4*)&sXT[k * 68 + ty * 8];
            float4 a1 = *(const float4*)&sXT[k * 68 + ty * 8 + 4];
            float4 w  = *(const float4*)&sW [k * 64 + tx * 4];
            float ar[8] = {a0.x, a0.y, a0.z, a0.w, a1.x, a1.y, a1.z, a1.w};
            #pragma unroll
            for (int r = 0; r < 8; ++r) {
                acc[r][0] += ar[r] * w.x;
                acc[r][1] += ar[r] * w.y;
                acc[r][2] += ar[r] * w.z;
                acc[r][3] += ar[r] * w.w;
            }
        }
    }

    #pragma unroll
    for (int r = 0; r < 8; ++r) {
        int grow = row0 + ty * 8 + r;
        if (grow < NIQ) {
            float4 o = make_float4(acc[r][0], acc[r][1], acc[r][2], acc[r][3]);
            ((float4*)g_xi)[(size_t)grow * 16 + tx] = o;
        }
    }
}

// ---------------- fused bidirectional scatter (vector RED) ---------------------
// 16 threads per edge; each thread moves one float4 per direction with a single
// red.global.add.v4.f32 (4x fewer reduction instructions than scalar atomics).
__device__ __forceinline__ void red_add_v4(float* p, float4 v) {
    asm volatile("red.global.add.v4.f32 [%0], {%1, %2, %3, %4};"
                 :: "l"(p), "f"(v.x), "f"(v.y), "f"(v.z), "f"(v.w) : "memory");
}

__global__ void k_scatter(const float4* __restrict__ utab, const float4* __restrict__ itab,
                          const int* __restrict__ src, const int* __restrict__ dst,
                          float* __restrict__ aggu, float* __restrict__ aggi)
{
    int t = blockIdx.x * blockDim.x + threadIdx.x;   // EQ*16 exactly
    int e = t >> 4;
    int q = t & 15;
    int lane = threadIdx.x & 31;

    int s = 0, d = 0;
    if ((lane & 15) == 0) { s = src[e]; d = dst[e]; }
    s = __shfl_sync(0xffffffffu, s, lane & 16);
    d = __shfl_sync(0xffffffffu, d, lane & 16);

    float4 uv = utab[(size_t)s * 16 + q];
    red_add_v4(aggi + (size_t)d * 64 + q * 4, uv);

    float4 iv = itab[(size_t)d * 16 + q];
    red_add_v4(aggu + (size_t)s * 64 + q * 4, iv);
}

// ---------------- fused dual GEMM combine --------------------------------------
// out = act( (agg * 1/max(deg,1)) @ Wl + x @ Wr + b )
// block = 128 threads (16 tx x 8 ty), tile = 64 rows x 64 cols,
// micro-tile 8 rows x 4 cols per thread. Inputs staged transposed (pitch 68).
template <bool RELU>
__global__ __launch_bounds__(128) void k_combine(
    int n, const float* __restrict__ agg, const float* __restrict__ deg,
    const float* __restrict__ x, const float* __restrict__ Wl,
    const float* __restrict__ Wr, const float* __restrict__ b,
    float* __restrict__ out)
{
    extern __shared__ float sm[];
    float* sWl = sm;                 // 4096
    float* sWr = sm + 4096;          // 4096
    float* sB  = sm + 8192;          // 64
    float* saT = sm + 8192 + 64;     // 64 x 68
    float* sxT = saT + 64 * 68;      // 64 x 68

    const int tid = threadIdx.x;
    const int tx = tid & 15;
    const int ty = tid >> 4;
    const int row0 = blockIdx.x * 64;

    for (int i = tid; i < 4096; i += 128) { sWl[i] = Wl[i]; sWr[i] = Wr[i]; }
    if (tid < 64) sB[tid] = b[tid];

    // stage 64x64 tiles of agg (pre-scaled by 1/deg) and x, transposed
    for (int i = tid; i < 1024; i += 128) {
        int r = i >> 4, c4 = i & 15;
        int grow = row0 + r;
        float4 av, xv;
        float rd = 1.f;
        if (grow < n) {
            av = ((const float4*)agg)[(size_t)grow * 16 + c4];
            xv = ((const float4*)x)[(size_t)grow * 16 + c4];
            rd = 1.f / fmaxf(deg[grow], 1.f);
        } else {
            av = make_float4(0.f, 0.f, 0.f, 0.f);
            xv = av;
        }
        int c = c4 * 4;
        saT[(c + 0) * 68 + r] = av.x * rd;
        saT[(c + 1) * 68 + r] = av.y * rd;
        saT[(c + 2) * 68 + r] = av.z * rd;
        saT[(c + 3) * 68 + r] = av.w * rd;
        sxT[(c + 0) * 68 + r] = xv.x;
        sxT[(c + 1) * 68 + r] = xv.y;
        sxT[(c + 2) * 68 + r] = xv.z;
        sxT[(c + 3) * 68 + r] = xv.w;
    }
    __syncthreads();

    float acc[8][4];
    {
        float4 bv = *(const float4*)&sB[tx * 4];
        #pragma unroll
        for (int r = 0; r < 8; ++r) {
            acc[r][0] = bv.x; acc[r][1] = bv.y; acc[r][2] = bv.z; acc[r][3] = bv.w;
        }
    }

    #pragma unroll 4
    for (int k = 0; k < 64; ++k) {
        float4 a0 = *(const float4*)&saT[k * 68 + ty * 8];
        float4 a1 = *(const float4*)&saT[k * 68 + ty * 8 + 4];
        float4 wl = *(const float4*)&sWl[k * 64 + tx * 4];
        float4 x0 = *(const float4*)&sxT[k * 68 + ty * 8];
        float4 x1 = *(const float4*)&sxT[k * 68 + ty * 8 + 4];
        float4 wr = *(const float4*)&sWr[k * 64 + tx * 4];

        float ar[8] = {a0.x, a0.y, a0.z, a0.w, a1.x, a1.y, a1.z, a1.w};
        float xr[8] = {x0.x, x0.y, x0.z, x0.w, x1.x, x1.y, x1.z, x1.w};
        float wlc[4] = {wl.x, wl.y, wl.z, wl.w};
        float wrc[4] = {wr.x, wr.y, wr.z, wr.w};
        #pragma unroll
        for (int r = 0; r < 8; ++r)
            #pragma unroll
            for (int c = 0; c < 4; ++c)
                acc[r][c] += ar[r] * wlc[c] + xr[r] * wrc[c];
    }

    #pragma unroll
    for (int r = 0; r < 8; ++r) {
        int grow = row0 + ty * 8 + r;
        if (grow < n) {
            float4 o;
            o.x = acc[r][0]; o.y = acc[r][1]; o.z = acc[r][2]; o.w = acc[r][3];
            if (RELU) {
                o.x = fmaxf(o.x, 0.f); o.y = fmaxf(o.y, 0.f);
                o.z = fmaxf(o.z, 0.f); o.w = fmaxf(o.w, 0.f);
            }
            ((float4*)out)[(size_t)grow * 16 + tx] = o;
        }
    }
}

// ---------------- dot-product predictor ----------------------------------------
// 8 lanes per edge, each lane 8 floats (2 float4) per side, shfl tree reduce.
__global__ void k_predict(const float* __restrict__ hu, const float* __restrict__ hi,
                          const int* __restrict__ ls, const int* __restrict__ ld,
                          float* __restrict__ out)
{
    int t = blockIdx.x * blockDim.x + threadIdx.x;   // ELQ*8 exactly
    int e = t >> 3;
    int q = t & 7;
    int s = ls[e];
    int d = ld[e];
    const float4* hu4 = (const float4*)hu;
    const float4* hi4 = (const float4*)hi;
    float4 a0 = hu4[(size_t)s * 16 + q * 2];
    float4 a1 = hu4[(size_t)s * 16 + q * 2 + 1];
    float4 b0 = hi4[(size_t)d * 16 + q * 2];
    float4 b1 = hi4[(size_t)d * 16 + q * 2 + 1];
    float p = a0.x * b0.x + a0.y * b0.y + a0.z * b0.z + a0.w * b0.w
            + a1.x * b1.x + a1.y * b1.y + a1.z * b1.z + a1.w * b1.w;
    p += __shfl_down_sync(0xffffffffu, p, 4);
    p += __shfl_down_sync(0xffffffffu, p, 2);
    p += __shfl_down_sync(0xffffffffu, p, 1);
    if (q == 0) out[e] = p;
}

// ---------------- host orchestration -------------------------------------------
extern "C" void kernel_launch(void* const* d_in, const int* in_sizes, int n_in,
                              void* d_out, int out_size)
{
    const float* user_emb   = (const float*)d_in[0];
    const float* item_x     = (const float*)d_in[1];
    const float* item_lin_w = (const float*)d_in[2];
    const float* item_lin_b = (const float*)d_in[3];
    const float* Wl1_ui = (const float*)d_in[4];
    const float* Wr1_ui = (const float*)d_in[5];
    const float* b1_ui  = (const float*)d_in[6];
    const float* Wl1_iu = (const float*)d_in[7];
    const float* Wr1_iu = (const float*)d_in[8];
    const float* b1_iu  = (const float*)d_in[9];
    const float* Wl2_ui = (const float*)d_in[10];
    const float* Wr2_ui = (const float*)d_in[11];
    const float* b2_ui  = (const float*)d_in[12];
    const float* Wl2_iu = (const float*)d_in[13];
    const float* Wr2_iu = (const float*)d_in[14];
    const float* b2_iu  = (const float*)d_in[15];
    const int* user_node_id = (const int*)d_in[16];
    const int* esrc = (const int*)d_in[17];
    const int* edst = (const int*)d_in[18];
    const int* lsrc = (const int*)d_in[19];
    const int* ldst = (const int*)d_in[20];
    float* out = (float*)d_out;

    float *p_xu, *p_xi, *p_aggu, *p_aggi, *p_hu, *p_hi, *p_hu2, *p_hi2, *p_degu, *p_degi;
    cudaGetSymbolAddress((void**)&p_xu,   g_xu);
    cudaGetSymbolAddress((void**)&p_xi,   g_xi);
    cudaGetSymbolAddress((void**)&p_aggu, g_aggu);
    cudaGetSymbolAddress((void**)&p_aggi, g_aggi);
    cudaGetSymbolAddress((void**)&p_hu,   g_hu);
    cudaGetSymbolAddress((void**)&p_hi,   g_hi);
    cudaGetSymbolAddress((void**)&p_hu2,  g_hu2);
    cudaGetSymbolAddress((void**)&p_hi2,  g_hi2);
    cudaGetSymbolAddress((void**)&p_degu, g_degu);
    cudaGetSymbolAddress((void**)&p_degi, g_degi);

    const int SMEM_CMB = (8192 + 64 + 2 * 64 * 68) * 4;    // 67840 B
    cudaFuncSetAttribute(k_combine<true>, cudaFuncAttributeMaxDynamicSharedMemorySize, SMEM_CMB);
    cudaFuncSetAttribute(k_combine<false>,cudaFuncAttributeMaxDynamicSharedMemorySize, SMEM_CMB);

    // degrees (shared by both layers)
    cudaMemsetAsync(p_degu, 0, NUQ * sizeof(float));
    cudaMemsetAsync(p_degi, 0, NIQ * sizeof(float));
    k_degree<<<(EQ + 255) / 256, 256>>>(esrc, edst);

    // input features
    k_gather<<<NUQ * 16 / 256, 256>>>((const float4*)user_emb, user_node_id);
    k_item_gemm<<<(NIQ + 63) / 64, 128>>>(item_x, item_lin_w, item_lin_b);

    // ---- layer 1 ----
    cudaMemsetAsync(p_aggu, 0, (size_t)NUQ * DQ * sizeof(float));
    cudaMemsetAsync(p_aggi, 0, (size_t)NIQ * DQ * sizeof(float));
    k_scatter<<<EQ * 16 / 256, 256>>>((const float4*)p_xu, (const float4*)p_xi,
                                      esrc, edst, p_aggu, p_aggi);
    k_combine<true><<<(NIQ + 63) / 64, 128, SMEM_CMB>>>(NIQ, p_aggi, p_degi, p_xi,
                                                        Wl1_ui, Wr1_ui, b1_ui, p_hi);
    k_combine<true><<<(NUQ + 63) / 64, 128, SMEM_CMB>>>(NUQ, p_aggu, p_degu, p_xu,
                                                        Wl1_iu, Wr1_iu, b1_iu, p_hu);

    // ---- layer 2 ----
    cudaMemsetAsync(p_aggu, 0, (size_t)NUQ * DQ * sizeof(float));
    cudaMemsetAsync(p_aggi, 0, (size_t)NIQ * DQ * sizeof(float));
    k_scatter<<<EQ * 16 / 256, 256>>>((const float4*)p_hu, (const float4*)p_hi,
                                      esrc, edst, p_aggu, p_aggi);
    k_combine<false><<<(NIQ + 63) / 64, 128, SMEM_CMB>>>(NIQ, p_aggi, p_degi, p_hi,
                                                         Wl2_ui, Wr2_ui, b2_ui, p_hi2);
    k_combine<false><<<(NUQ + 63) / 64, 128, SMEM_CMB>>>(NUQ, p_aggu, p_degu, p_hu,
                                                         Wl2_iu, Wr2_iu, b2_iu, p_hu2);

    // ---- predictor ----
    k_predict<<<ELQ * 8 / 256, 256>>>(p_hu2, p_hi2, lsrc, ldst, out);
}

// round 4
// speedup vs baseline: 2.1540x; 1.2015x over previous
#include <cuda_runtime.h>

#define NUQ 500000
#define NIQ 100000
#define FQ  300
#define DQ  64
#define EQ  2000000
#define ELQ 1000000
#define NB_SCAN 123            // ceil(NUQ / 4096)

// ---------------- scratch (device globals; no allocations allowed) -------------
__device__ __align__(16) float g_xu  [NUQ * DQ];   // user input features
__device__ __align__(16) float g_xi  [NIQ * DQ];   // item input features
__device__ __align__(16) float g_aggu[NUQ * DQ];   // user aggregate (streamed)
__device__ __align__(16) float g_aggi[NIQ * DQ];   // item aggregate (atomics)
__device__ __align__(16) float g_hu  [NUQ * DQ];
__device__ __align__(16) float g_hi  [NIQ * DQ];
__device__ __align__(16) float g_hu2 [NUQ * DQ];
__device__ __align__(16) float g_hi2 [NIQ * DQ];

// CSR-by-src machinery
__device__ int g_cntu  [NUQ];      // user degree (hist)
__device__ int g_cnti  [NIQ];      // item degree (hist)
__device__ int g_pre   [NUQ];      // per-block exclusive prefix
__device__ int g_rowptr[NUQ];      // global exclusive prefix (CSR row starts)
__device__ int g_cursor[NUQ];      // placement cursors
__device__ int g_bsum  [128];
__device__ int g_boff  [128];
__device__ int g_dsts  [EQ];       // dst ids sorted by src

// ---------------- histogram: degrees for both sides ----------------------------
__global__ void k_hist(const int* __restrict__ src, const int* __restrict__ dst) {
    int i = blockIdx.x * blockDim.x + threadIdx.x;
    if (i < EQ) {
        atomicAdd(&g_cntu[src[i]], 1);
        atomicAdd(&g_cnti[dst[i]], 1);
    }
}

// ---------------- hierarchical exclusive scan of g_cntu ------------------------
// s1: 512 threads/block, 8 elems/thread -> 4096 per block
__global__ __launch_bounds__(512) void k_scan1() {
    __shared__ int swarp[16];
    const int t = threadIdx.x;
    const int base = blockIdx.x * 4096 + t * 8;
    int v[8], s = 0;
    #pragma unroll
    for (int j = 0; j < 8; ++j) {
        v[j] = (base + j < NUQ) ? g_cntu[base + j] : 0;
        s += v[j];
    }
    const int lane = t & 31, w = t >> 5;
    int x = s;
    #pragma unroll
    for (int off = 1; off < 32; off <<= 1) {
        int y = __shfl_up_sync(0xffffffffu, x, off);
        if (lane >= off) x += y;
    }
    if (lane == 31) swarp[w] = x;
    __syncthreads();
    if (w == 0) {
        int y = (lane < 16) ? swarp[lane] : 0;
        #pragma unroll
        for (int off = 1; off < 16; off <<= 1) {
            int z = __shfl_up_sync(0xffffffffu, y, off);
            if (lane >= off) y += z;
        }
        if (lane < 16) swarp[lane] = y;   // inclusive over warp sums
    }
    __syncthreads();
    int run = (w > 0 ? swarp[w - 1] : 0) + (x - s);   // exclusive prefix for this thread
    #pragma unroll
    for (int j = 0; j < 8; ++j) {
        if (base + j < NUQ) g_pre[base + j] = run;
        run += v[j];
    }
    if (t == 0) g_bsum[blockIdx.x] = swarp[15];
}

__global__ void k_scan2() {
    if (threadIdx.x == 0 && blockIdx.x == 0) {
        int a = 0;
        for (int i = 0; i < NB_SCAN; ++i) { g_boff[i] = a; a += g_bsum[i]; }
    }
}

__global__ void k_scan3() {
    int i = blockIdx.x * blockDim.x + threadIdx.x;
    if (i < NUQ) {
        int r = g_pre[i] + g_boff[i >> 12];
        g_rowptr[i] = r;
        g_cursor[i] = r;
    }
}

// ---------------- edge placement (counting-sort by src) ------------------------
__global__ void k_place(const int* __restrict__ src, const int* __restrict__ dst) {
    int i = blockIdx.x * blockDim.x + threadIdx.x;
    if (i < EQ) {
        int s = src[i];
        int pos = atomicAdd(&g_cursor[s], 1);
        g_dsts[pos] = dst[i];
    }
}

// ---------------- user embedding gather ---------------------------------------
__global__ void k_gather(const float4* __restrict__ emb, const int* __restrict__ nid) {
    int i = blockIdx.x * blockDim.x + threadIdx.x;   // exactly NUQ*16
    int row = i >> 4;
    int id = nid[row];
    ((float4*)g_xu)[i] = emb[(size_t)id * 16 + (i & 15)];
}

// ---------------- item linear GEMM: xi = item_x @ W + b ------------------------
__global__ __launch_bounds__(128) void k_item_gemm(
    const float* __restrict__ X, const float* __restrict__ W, const float* __restrict__ bias)
{
    __shared__ float sW [60 * 64];
    __shared__ float sXT[60 * 68];

    const int tid = threadIdx.x;
    const int tx  = tid & 15;
    const int ty  = tid >> 4;
    const int row0 = blockIdx.x * 64;

    const float4 bv = ((const float4*)bias)[tx];
    float acc[8][4];
    #pragma unroll
    for (int r = 0; r < 8; ++r) {
        acc[r][0] = bv.x; acc[r][1] = bv.y; acc[r][2] = bv.z; acc[r][3] = bv.w;
    }

    for (int k0 = 0; k0 < FQ; k0 += 60) {
        __syncthreads();
        const float4* Wg = (const float4*)(W + k0 * 64);
        for (int i = tid; i < 960; i += 128)
            ((float4*)sW)[i] = Wg[i];
        for (int i = tid; i < 960; i += 128) {
            int r  = i / 15;
            int c4 = i - r * 15;
            int grow = row0 + r;
            float4 v = make_float4(0.f, 0.f, 0.f, 0.f);
            if (grow < NIQ)
                v = *(const float4*)(X + (size_t)grow * FQ + k0 + c4 * 4);
            int k = c4 * 4;
            sXT[(k + 0) * 68 + r] = v.x;
            sXT[(k + 1) * 68 + r] = v.y;
            sXT[(k + 2) * 68 + r] = v.z;
            sXT[(k + 3) * 68 + r] = v.w;
        }
        __syncthreads();

        #pragma unroll 6
        for (int k = 0; k < 60; ++k) {
            float4 a0 = *(const float4*)&sXT[k * 68 + ty * 8];
            float4 a1 = *(const float4*)&sXT[k * 68 + ty * 8 + 4];
            float4 w  = *(const float4*)&sW [k * 64 + tx * 4];
            float ar[8] = {a0.x, a0.y, a0.z, a0.w, a1.x, a1.y, a1.z, a1.w};
            #pragma unroll
            for (int r = 0; r < 8; ++r) {
                acc[r][0] += ar[r] * w.x;
                acc[r][1] += ar[r] * w.y;
                acc[r][2] += ar[r] * w.z;
                acc[r][3] += ar[r] * w.w;
            }
        }
    }

    #pragma unroll
    for (int r = 0; r < 8; ++r) {
        int grow = row0 + ty * 8 + r;
        if (grow < NIQ) {
            float4 o = make_float4(acc[r][0], acc[r][1], acc[r][2], acc[r][3]);
            ((float4*)g_xi)[(size_t)grow * 16 + tx] = o;
        }
    }
}

// ---------------- fused CSR aggregation (both directions) ----------------------
// Half-warp (16 lanes x float4) per user. User row read once (streaming),
// user agg written once (streaming, no memset/atomics). Item-side uses
// vector RED into the L2-resident aggi, item rows gathered from L2.
__device__ __forceinline__ void red_add_v4(float* p, float4 v) {
    asm volatile("red.global.add.v4.f32 [%0], {%1, %2, %3, %4};"
                 :: "l"(p), "f"(v.x), "f"(v.y), "f"(v.z), "f"(v.w) : "memory");
}

__global__ void k_csr_agg(const float4* __restrict__ utab, const float4* __restrict__ itab,
                          float4* __restrict__ aggu, float* __restrict__ aggi)
{
    int t = blockIdx.x * blockDim.x + threadIdx.x;   // NUQ*16 exactly
    int u = t >> 4;
    int q = t & 15;

    int beg = __ldg(&g_rowptr[u]);
    int cnt = __ldg(&g_cntu[u]);
    float4 vu = utab[(size_t)u * 16 + q];
    float4 acc = make_float4(0.f, 0.f, 0.f, 0.f);

    for (int e = beg; e < beg + cnt; ++e) {
        int d = __ldg(&g_dsts[e]);
        float4 iv = itab[(size_t)d * 16 + q];
        acc.x += iv.x; acc.y += iv.y; acc.z += iv.z; acc.w += iv.w;
        red_add_v4(aggi + (size_t)d * 64 + q * 4, vu);
    }
    aggu[(size_t)u * 16 + q] = acc;
}

// ---------------- fused dual GEMM combine --------------------------------------
// out = act( (agg * 1/max(deg,1)) @ Wl + x @ Wr + b )
template <bool RELU>
__global__ __launch_bounds__(128) void k_combine(
    int n, const float* __restrict__ agg, const int* __restrict__ deg,
    const float* __restrict__ x, const float* __restrict__ Wl,
    const float* __restrict__ Wr, const float* __restrict__ b,
    float* __restrict__ out)
{
    extern __shared__ float sm[];
    float* sWl = sm;                 // 4096
    float* sWr = sm + 4096;          // 4096
    float* sB  = sm + 8192;          // 64
    float* saT = sm + 8192 + 64;     // 64 x 68
    float* sxT = saT + 64 * 68;      // 64 x 68

    const int tid = threadIdx.x;
    const int tx = tid & 15;
    const int ty = tid >> 4;
    const int row0 = blockIdx.x * 64;

    for (int i = tid; i < 4096; i += 128) { sWl[i] = Wl[i]; sWr[i] = Wr[i]; }
    if (tid < 64) sB[tid] = b[tid];

    for (int i = tid; i < 1024; i += 128) {
        int r = i >> 4, c4 = i & 15;
        int grow = row0 + r;
        float4 av, xv;
        float rd = 1.f;
        if (grow < n) {
            av = ((const float4*)agg)[(size_t)grow * 16 + c4];
            xv = ((const float4*)x)[(size_t)grow * 16 + c4];
            rd = 1.f / fmaxf((float)deg[grow], 1.f);
        } else {
            av = make_float4(0.f, 0.f, 0.f, 0.f);
            xv = av;
        }
        int c = c4 * 4;
        saT[(c + 0) * 68 + r] = av.x * rd;
        saT[(c + 1) * 68 + r] = av.y * rd;
        saT[(c + 2) * 68 + r] = av.z * rd;
        saT[(c + 3) * 68 + r] = av.w * rd;
        sxT[(c + 0) * 68 + r] = xv.x;
        sxT[(c + 1) * 68 + r] = xv.y;
        sxT[(c + 2) * 68 + r] = xv.z;
        sxT[(c + 3) * 68 + r] = xv.w;
    }
    __syncthreads();

    float acc[8][4];
    {
        float4 bv = *(const float4*)&sB[tx * 4];
        #pragma unroll
        for (int r = 0; r < 8; ++r) {
            acc[r][0] = bv.x; acc[r][1] = bv.y; acc[r][2] = bv.z; acc[r][3] = bv.w;
        }
    }

    #pragma unroll 4
    for (int k = 0; k < 64; ++k) {
        float4 a0 = *(const float4*)&saT[k * 68 + ty * 8];
        float4 a1 = *(const float4*)&saT[k * 68 + ty * 8 + 4];
        float4 wl = *(const float4*)&sWl[k * 64 + tx * 4];
        float4 x0 = *(const float4*)&sxT[k * 68 + ty * 8];
        float4 x1 = *(const float4*)&sxT[k * 68 + ty * 8 + 4];
        float4 wr = *(const float4*)&sWr[k * 64 + tx * 4];

        float ar[8] = {a0.x, a0.y, a0.z, a0.w, a1.x, a1.y, a1.z, a1.w};
        float xr[8] = {x0.x, x0.y, x0.z, x0.w, x1.x, x1.y, x1.z, x1.w};
        float wlc[4] = {wl.x, wl.y, wl.z, wl.w};
        float wrc[4] = {wr.x, wr.y, wr.z, wr.w};
        #pragma unroll
        for (int r = 0; r < 8; ++r)
            #pragma unroll
            for (int c = 0; c < 4; ++c)
                acc[r][c] += ar[r] * wlc[c] + xr[r] * wrc[c];
    }

    #pragma unroll
    for (int r = 0; r < 8; ++r) {
        int grow = row0 + ty * 8 + r;
        if (grow < n) {
            float4 o;
            o.x = acc[r][0]; o.y = acc[r][1]; o.z = acc[r][2]; o.w = acc[r][3];
            if (RELU) {
                o.x = fmaxf(o.x, 0.f); o.y = fmaxf(o.y, 0.f);
                o.z = fmaxf(o.z, 0.f); o.w = fmaxf(o.w, 0.f);
            }
            ((float4*)out)[(size_t)grow * 16 + tx] = o;
        }
    }
}

// ---------------- dot-product predictor ----------------------------------------
__global__ void k_predict(const float* __restrict__ hu, const float* __restrict__ hi,
                          const int* __restrict__ ls, const int* __restrict__ ld,
                          float* __restrict__ out)
{
    int t = blockIdx.x * blockDim.x + threadIdx.x;   // ELQ*8 exactly
    int e = t >> 3;
    int q = t & 7;
    int s = ls[e];
    int d = ld[e];
    const float4* hu4 = (const float4*)hu;
    const float4* hi4 = (const float4*)hi;
    float4 a0 = hu4[(size_t)s * 16 + q * 2];
    float4 a1 = hu4[(size_t)s * 16 + q * 2 + 1];
    float4 b0 = hi4[(size_t)d * 16 + q * 2];
    float4 b1 = hi4[(size_t)d * 16 + q * 2 + 1];
    float p = a0.x * b0.x + a0.y * b0.y + a0.z * b0.z + a0.w * b0.w
            + a1.x * b1.x + a1.y * b1.y + a1.z * b1.z + a1.w * b1.w;
    p += __shfl_down_sync(0xffffffffu, p, 4);
    p += __shfl_down_sync(0xffffffffu, p, 2);
    p += __shfl_down_sync(0xffffffffu, p, 1);
    if (q == 0) out[e] = p;
}

// ---------------- host orchestration -------------------------------------------
extern "C" void kernel_launch(void* const* d_in, const int* in_sizes, int n_in,
                              void* d_out, int out_size)
{
    const float* user_emb   = (const float*)d_in[0];
    const float* item_x     = (const float*)d_in[1];
    const float* item_lin_w = (const float*)d_in[2];
    const float* item_lin_b = (const float*)d_in[3];
    const float* Wl1_ui = (const float*)d_in[4];
    const float* Wr1_ui = (const float*)d_in[5];
    const float* b1_ui  = (const float*)d_in[6];
    const float* Wl1_iu = (const float*)d_in[7];
    const float* Wr1_iu = (const float*)d_in[8];
    const float* b1_iu  = (const float*)d_in[9];
    const float* Wl2_ui = (const float*)d_in[10];
    const float* Wr2_ui = (const float*)d_in[11];
    const float* b2_ui  = (const float*)d_in[12];
    const float* Wl2_iu = (const float*)d_in[13];
    const float* Wr2_iu = (const float*)d_in[14];
    const float* b2_iu  = (const float*)d_in[15];
    const int* user_node_id = (const int*)d_in[16];
    const int* esrc = (const int*)d_in[17];
    const int* edst = (const int*)d_in[18];
    const int* lsrc = (const int*)d_in[19];
    const int* ldst = (const int*)d_in[20];
    float* out = (float*)d_out;

    float *p_xu, *p_xi, *p_aggu, *p_aggi, *p_hu, *p_hi, *p_hu2, *p_hi2;
    int *p_cntu, *p_cnti;
    cudaGetSymbolAddress((void**)&p_xu,   g_xu);
    cudaGetSymbolAddress((void**)&p_xi,   g_xi);
    cudaGetSymbolAddress((void**)&p_aggu, g_aggu);
    cudaGetSymbolAddress((void**)&p_aggi, g_aggi);
    cudaGetSymbolAddress((void**)&p_hu,   g_hu);
    cudaGetSymbolAddress((void**)&p_hi,   g_hi);
    cudaGetSymbolAddress((void**)&p_hu2,  g_hu2);
    cudaGetSymbolAddress((void**)&p_hi2,  g_hi2);
    cudaGetSymbolAddress((void**)&p_cntu, g_cntu);
    cudaGetSymbolAddress((void**)&p_cnti, g_cnti);

    const int SMEM_CMB = (8192 + 64 + 2 * 64 * 68) * 4;    // 67840 B
    cudaFuncSetAttribute(k_combine<true>, cudaFuncAttributeMaxDynamicSharedMemorySize, SMEM_CMB);
    cudaFuncSetAttribute(k_combine<false>,cudaFuncAttributeMaxDynamicSharedMemorySize, SMEM_CMB);

    // ---- CSR build (by src) + degrees for both sides ----
    cudaMemsetAsync(p_cntu, 0, NUQ * sizeof(int));
    cudaMemsetAsync(p_cnti, 0, NIQ * sizeof(int));
    k_hist<<<(EQ + 255) / 256, 256>>>(esrc, edst);
    k_scan1<<<NB_SCAN, 512>>>();
    k_scan2<<<1, 32>>>();
    k_scan3<<<(NUQ + 255) / 256, 256>>>();
    k_place<<<(EQ + 255) / 256, 256>>>(esrc, edst);

    // ---- input features ----
    k_gather<<<NUQ * 16 / 256, 256>>>((const float4*)user_emb, user_node_id);
    k_item_gemm<<<(NIQ + 63) / 64, 128>>>(item_x, item_lin_w, item_lin_b);

    // ---- layer 1 ----
    cudaMemsetAsync(p_aggi, 0, (size_t)NIQ * DQ * sizeof(float));
    k_csr_agg<<<NUQ * 16 / 256, 256>>>((const float4*)p_xu, (const float4*)p_xi,
                                       (float4*)p_aggu, p_aggi);
    k_combine<true><<<(NIQ + 63) / 64, 128, SMEM_CMB>>>(NIQ, p_aggi, p_cnti, p_xi,
                                                        Wl1_ui, Wr1_ui, b1_ui, p_hi);
    k_combine<true><<<(NUQ + 63) / 64, 128, SMEM_CMB>>>(NUQ, p_aggu, p_cntu, p_xu,
                                                        Wl1_iu, Wr1_iu, b1_iu, p_hu);

    // ---- layer 2 ----
    cudaMemsetAsync(p_aggi, 0, (size_t)NIQ * DQ * sizeof(float));
    k_csr_agg<<<NUQ * 16 / 256, 256>>>((const float4*)p_hu, (const float4*)p_hi,
                                       (float4*)p_aggu, p_aggi);
    k_combine<false><<<(NIQ + 63) / 64, 128, SMEM_CMB>>>(NIQ, p_aggi, p_cnti, p_hi,
                                                         Wl2_ui, Wr2_ui, b2_ui, p_hi2);
    k_combine<false><<<(NUQ + 63) / 64, 128, SMEM_CMB>>>(NUQ, p_aggu, p_cntu, p_hu,
                                                         Wl2_iu, Wr2_iu, b2_iu, p_hu2);

    // ---- predictor ----
    k_predict<<<ELQ * 8 / 256, 256>>>(p_hu2, p_hi2, lsrc, ldst, out);
}

// round 5
// speedup vs baseline: 2.3103x; 1.0726x over previous
#include <cuda_runtime.h>

#define NUQ 500000
#define NIQ 100000
#define FQ  300
#define DQ  64
#define EQ  2000000
#define ELQ 1000000
#define NB_SCAN 123            // ceil(NUQ / 4096)

// ---------------- scratch (device globals; no allocations allowed) -------------
__device__ __align__(16) float g_xu  [NUQ * DQ];   // user input features
__device__ __align__(16) float g_xi  [NIQ * DQ];   // item input features
__device__ __align__(16) float g_itT [NIQ * DQ];   // transformed item table (x_i @ Wl_iu)
__device__ __align__(16) float g_aggu[NUQ * DQ];   // user aggregate of TRANSFORMED items
__device__ __align__(16) float g_aggi[NIQ * DQ];   // item aggregate of raw user rows
__device__ __align__(16) float g_hu  [NUQ * DQ];
__device__ __align__(16) float g_hi  [NIQ * DQ];
__device__ __align__(16) float g_hu2 [NUQ * DQ];
__device__ __align__(16) float g_hi2 [NIQ * DQ];
__device__ float g_zero64[DQ];                     // stays zero (zero-initialized)

// CSR-by-src machinery
__device__ int g_cntu  [NUQ];
__device__ int g_cnti  [NIQ];
__device__ int g_pre   [NUQ];
__device__ int g_rowptr[NUQ];
__device__ int g_cursor[NUQ];
__device__ int g_bsum  [128];
__device__ int g_boff  [128];
__device__ int g_dsts  [EQ];

// ---------------- histogram ----------------------------------------------------
__global__ void k_hist(const int* __restrict__ src, const int* __restrict__ dst) {
    int i = blockIdx.x * blockDim.x + threadIdx.x;
    if (i < EQ) {
        atomicAdd(&g_cntu[src[i]], 1);
        atomicAdd(&g_cnti[dst[i]], 1);
    }
}

// ---------------- hierarchical exclusive scan of g_cntu ------------------------
__global__ __launch_bounds__(512) void k_scan1() {
    __shared__ int swarp[16];
    const int t = threadIdx.x;
    const int base = blockIdx.x * 4096 + t * 8;
    int v[8], s = 0;
    #pragma unroll
    for (int j = 0; j < 8; ++j) {
        v[j] = (base + j < NUQ) ? g_cntu[base + j] : 0;
        s += v[j];
    }
    const int lane = t & 31, w = t >> 5;
    int x = s;
    #pragma unroll
    for (int off = 1; off < 32; off <<= 1) {
        int y = __shfl_up_sync(0xffffffffu, x, off);
        if (lane >= off) x += y;
    }
    if (lane == 31) swarp[w] = x;
    __syncthreads();
    if (w == 0) {
        int y = (lane < 16) ? swarp[lane] : 0;
        #pragma unroll
        for (int off = 1; off < 16; off <<= 1) {
            int z = __shfl_up_sync(0xffffffffu, y, off);
            if (lane >= off) y += z;
        }
        if (lane < 16) swarp[lane] = y;
    }
    __syncthreads();
    int run = (w > 0 ? swarp[w - 1] : 0) + (x - s);
    #pragma unroll
    for (int j = 0; j < 8; ++j) {
        if (base + j < NUQ) g_pre[base + j] = run;
        run += v[j];
    }
    if (t == 0) g_bsum[blockIdx.x] = swarp[15];
}

__global__ void k_scan2() {
    if (threadIdx.x == 0 && blockIdx.x == 0) {
        int a = 0;
        for (int i = 0; i < NB_SCAN; ++i) { g_boff[i] = a; a += g_bsum[i]; }
    }
}

__global__ void k_scan3() {
    int i = blockIdx.x * blockDim.x + threadIdx.x;
    if (i < NUQ) {
        int r = g_pre[i] + g_boff[i >> 12];
        g_rowptr[i] = r;
        g_cursor[i] = r;
    }
}

__global__ void k_place(const int* __restrict__ src, const int* __restrict__ dst) {
    int i = blockIdx.x * blockDim.x + threadIdx.x;
    if (i < EQ) {
        int s = src[i];
        int pos = atomicAdd(&g_cursor[s], 1);
        g_dsts[pos] = dst[i];
    }
}

// ---------------- user embedding gather ---------------------------------------
__global__ void k_gather(const float4* __restrict__ emb, const int* __restrict__ nid) {
    int i = blockIdx.x * blockDim.x + threadIdx.x;   // exactly NUQ*16
    int row = i >> 4;
    int id = nid[row];
    ((float4*)g_xu)[i] = emb[(size_t)id * 16 + (i & 15)];
}

// ---------------- item linear GEMM: xi = item_x @ W + b ------------------------
__global__ __launch_bounds__(128) void k_item_gemm(
    const float* __restrict__ X, const float* __restrict__ W, const float* __restrict__ bias)
{
    __shared__ float sW [60 * 64];
    __shared__ float sXT[60 * 68];

    const int tid = threadIdx.x;
    const int tx  = tid & 15;
    const int ty  = tid >> 4;
    const int row0 = blockIdx.x * 64;

    const float4 bv = ((const float4*)bias)[tx];
    float acc[8][4];
    #pragma unroll
    for (int r = 0; r < 8; ++r) {
        acc[r][0] = bv.x; acc[r][1] = bv.y; acc[r][2] = bv.z; acc[r][3] = bv.w;
    }

    for (int k0 = 0; k0 < FQ; k0 += 60) {
        __syncthreads();
        const float4* Wg = (const float4*)(W + k0 * 64);
        for (int i = tid; i < 960; i += 128)
            ((float4*)sW)[i] = Wg[i];
        for (int i = tid; i < 960; i += 128) {
            int r  = i / 15;
            int c4 = i - r * 15;
            int grow = row0 + r;
            float4 v = make_float4(0.f, 0.f, 0.f, 0.f);
            if (grow < NIQ)
                v = *(const float4*)(X + (size_t)grow * FQ + k0 + c4 * 4);
            int k = c4 * 4;
            sXT[(k + 0) * 68 + r] = v.x;
            sXT[(k + 1) * 68 + r] = v.y;
            sXT[(k + 2) * 68 + r] = v.z;
            sXT[(k + 3) * 68 + r] = v.w;
        }
        __syncthreads();

        #pragma unroll 6
        for (int k = 0; k < 60; ++k) {
            float4 a0 = *(const float4*)&sXT[k * 68 + ty * 8];
            float4 a1 = *(const float4*)&sXT[k * 68 + ty * 8 + 4];
            float4 w  = *(const float4*)&sW [k * 64 + tx * 4];
            float ar[8] = {a0.x, a0.y, a0.z, a0.w, a1.x, a1.y, a1.z, a1.w};
            #pragma unroll
            for (int r = 0; r < 8; ++r) {
                acc[r][0] += ar[r] * w.x;
                acc[r][1] += ar[r] * w.y;
                acc[r][2] += ar[r] * w.z;
                acc[r][3] += ar[r] * w.w;
            }
        }
    }

    #pragma unroll
    for (int r = 0; r < 8; ++r) {
        int grow = row0 + ty * 8 + r;
        if (grow < NIQ) {
            float4 o = make_float4(acc[r][0], acc[r][1], acc[r][2], acc[r][3]);
            ((float4*)g_xi)[(size_t)grow * 16 + tx] = o;
        }
    }
}

// ---------------- fused CSR aggregation (both directions) ----------------------
// Half-warp (16 lanes x float4) per user. Gathers TRANSFORMED item rows for the
// user aggregate (streamed out, no atomics); scatters RAW user rows to items.
__device__ __forceinline__ void red_add_v4(float* p, float4 v) {
    asm volatile("red.global.add.v4.f32 [%0], {%1, %2, %3, %4};"
                 :: "l"(p), "f"(v.x), "f"(v.y), "f"(v.z), "f"(v.w) : "memory");
}

__global__ void k_csr_agg(const float4* __restrict__ utab, const float4* __restrict__ itabT,
                          float4* __restrict__ aggu, float* __restrict__ aggi)
{
    int t = blockIdx.x * blockDim.x + threadIdx.x;   // NUQ*16 exactly
    int u = t >> 4;
    int q = t & 15;

    int beg = __ldg(&g_rowptr[u]);
    int cnt = __ldg(&g_cntu[u]);
    float4 vu = utab[(size_t)u * 16 + q];
    float4 acc = make_float4(0.f, 0.f, 0.f, 0.f);

    for (int e = beg; e < beg + cnt; ++e) {
        int d = __ldg(&g_dsts[e]);
        float4 iv = itabT[(size_t)d * 16 + q];
        acc.x += iv.x; acc.y += iv.y; acc.z += iv.z; acc.w += iv.w;
        red_add_v4(aggi + (size_t)d * 64 + q * 4, vu);
    }
    aggu[(size_t)u * 16 + q] = acc;
}

// ---------------- f32x2 single-GEMM combine ------------------------------------
// out = act( agg*rd + x @ W + b )   [AGG=true]
// out = x @ W + b                   [AGG=false, used for item pre-transform]
// Tile: 128 rows x 64 cols, 128 threads. Thread (tx=t&7, ty=t>>3) computes
// rows ty*8..+8 (as 4 packed row-pairs) x cols {tx + 8*ci}.
// Packed fma.rn.f32x2: A-pairs from transposed smem (ld 64-bit of 2 adjacent
// rows); W duplicated into both 32-bit lanes in smem (no per-iter packing).
template <bool RELU, bool AGG>
__global__ __launch_bounds__(128) void k_combine_u(
    int n, const float* __restrict__ agg, const int* __restrict__ deg,
    const float* __restrict__ x, const float* __restrict__ W,
    const float* __restrict__ b, float* __restrict__ out)
{
    extern __shared__ float sm[];
    double* sWd = (double*)sm;        // 4096 doubles (W duplicated) = 32 KB
    float*  saT = sm + 8192;          // 64 x 136 floats (x transposed)

    const int tid = threadIdx.x;
    const int tx = tid & 7;
    const int ty = tid >> 3;
    const int row0 = blockIdx.x * 128;

    // W duplicated into both lanes
    for (int i = tid; i < 4096; i += 128) {
        unsigned int wb = __float_as_uint(W[i]);
        unsigned long long wd = ((unsigned long long)wb << 32) | wb;
        sWd[i] = __longlong_as_double(wd);
    }
    // stage x tile transposed: saT[k][r], pitch 136
    for (int i = tid; i < 2048; i += 128) {
        int r = i >> 4, c4 = i & 15;
        int grow = row0 + r;
        float4 v = make_float4(0.f, 0.f, 0.f, 0.f);
        if (grow < n) v = ((const float4*)x)[(size_t)grow * 16 + c4];
        int k = c4 * 4;
        saT[(k + 0) * 136 + r] = v.x;
        saT[(k + 1) * 136 + r] = v.y;
        saT[(k + 2) * 136 + r] = v.z;
        saT[(k + 3) * 136 + r] = v.w;
    }
    __syncthreads();

    unsigned long long acc[4][8];
    #pragma unroll
    for (int ci = 0; ci < 8; ++ci) {
        unsigned int bb = __float_as_uint(b[tx + 8 * ci]);
        unsigned long long bp = ((unsigned long long)bb << 32) | bb;
        #pragma unroll
        for (int j = 0; j < 4; ++j) acc[j][ci] = bp;
    }

    #pragma unroll 4
    for (int k = 0; k < 64; ++k) {
        unsigned long long ap[4];
        const double* arow = (const double*)(saT + k * 136 + ty * 8);
        #pragma unroll
        for (int j = 0; j < 4; ++j) ap[j] = __double_as_longlong(arow[j]);
        #pragma unroll
        for (int ci = 0; ci < 8; ++ci) {
            unsigned long long wd = __double_as_longlong(sWd[k * 64 + tx + 8 * ci]);
            #pragma unroll
            for (int j = 0; j < 4; ++j)
                asm("fma.rn.f32x2 %0, %1, %2, %0;" : "+l"(acc[j][ci]) : "l"(ap[j]), "l"(wd));
        }
    }

    #pragma unroll
    for (int j = 0; j < 4; ++j) {
        int r0 = row0 + ty * 8 + 2 * j;
        int r1 = r0 + 1;
        float rd0 = 1.f, rd1 = 1.f;
        if (AGG) {
            if (r0 < n) rd0 = 1.f / fmaxf((float)deg[r0], 1.f);
            if (r1 < n) rd1 = 1.f / fmaxf((float)deg[r1], 1.f);
        }
        #pragma unroll
        for (int ci = 0; ci < 8; ++ci) {
            int c = tx + 8 * ci;
            float lo = __uint_as_float((unsigned int)(acc[j][ci] & 0xffffffffull));
            float hi = __uint_as_float((unsigned int)(acc[j][ci] >> 32));
            if (r0 < n) {
                float o = AGG ? lo + agg[(size_t)r0 * 64 + c] * rd0 : lo;
                if (RELU) o = fmaxf(o, 0.f);
                out[(size_t)r0 * 64 + c] = o;
            }
            if (r1 < n) {
                float o = AGG ? hi + agg[(size_t)r1 * 64 + c] * rd1 : hi;
                if (RELU) o = fmaxf(o, 0.f);
                out[(size_t)r1 * 64 + c] = o;
            }
        }
    }
}

// ---------------- dual GEMM combine (item side, 100k rows) ---------------------
template <bool RELU>
__global__ __launch_bounds__(128) void k_combine_i(
    int n, const float* __restrict__ agg, const int* __restrict__ deg,
    const float* __restrict__ x, const float* __restrict__ Wl,
    const float* __restrict__ Wr, const float* __restrict__ b,
    float* __restrict__ out)
{
    extern __shared__ float sm[];
    float* sWl = sm;
    float* sWr = sm + 4096;
    float* sB  = sm + 8192;
    float* saT = sm + 8192 + 64;
    float* sxT = saT + 64 * 68;

    const int tid = threadIdx.x;
    const int tx = tid & 15;
    const int ty = tid >> 4;
    const int row0 = blockIdx.x * 64;

    for (int i = tid; i < 4096; i += 128) { sWl[i] = Wl[i]; sWr[i] = Wr[i]; }
    if (tid < 64) sB[tid] = b[tid];

    for (int i = tid; i < 1024; i += 128) {
        int r = i >> 4, c4 = i & 15;
        int grow = row0 + r;
        float4 av, xv;
        float rd = 1.f;
        if (grow < n) {
            av = ((const float4*)agg)[(size_t)grow * 16 + c4];
            xv = ((const float4*)x)[(size_t)grow * 16 + c4];
            rd = 1.f / fmaxf((float)deg[grow], 1.f);
        } else {
            av = make_float4(0.f, 0.f, 0.f, 0.f);
            xv = av;
        }
        int c = c4 * 4;
        saT[(c + 0) * 68 + r] = av.x * rd;
        saT[(c + 1) * 68 + r] = av.y * rd;
        saT[(c + 2) * 68 + r] = av.z * rd;
        saT[(c + 3) * 68 + r] = av.w * rd;
        sxT[(c + 0) * 68 + r] = xv.x;
        sxT[(c + 1) * 68 + r] = xv.y;
        sxT[(c + 2) * 68 + r] = xv.z;
        sxT[(c + 3) * 68 + r] = xv.w;
    }
    __syncthreads();

    float acc[8][4];
    {
        float4 bv = *(const float4*)&sB[tx * 4];
        #pragma unroll
        for (int r = 0; r < 8; ++r) {
            acc[r][0] = bv.x; acc[r][1] = bv.y; acc[r][2] = bv.z; acc[r][3] = bv.w;
        }
    }

    #pragma unroll 4
    for (int k = 0; k < 64; ++k) {
        float4 a0 = *(const float4*)&saT[k * 68 + ty * 8];
        float4 a1 = *(const float4*)&saT[k * 68 + ty * 8 + 4];
        float4 wl = *(const float4*)&sWl[k * 64 + tx * 4];
        float4 x0 = *(const float4*)&sxT[k * 68 + ty * 8];
        float4 x1 = *(const float4*)&sxT[k * 68 + ty * 8 + 4];
        float4 wr = *(const float4*)&sWr[k * 64 + tx * 4];

        float ar[8] = {a0.x, a0.y, a0.z, a0.w, a1.x, a1.y, a1.z, a1.w};
        float xr[8] = {x0.x, x0.y, x0.z, x0.w, x1.x, x1.y, x1.z, x1.w};
        float wlc[4] = {wl.x, wl.y, wl.z, wl.w};
        float wrc[4] = {wr.x, wr.y, wr.z, wr.w};
        #pragma unroll
        for (int r = 0; r < 8; ++r)
            #pragma unroll
            for (int c = 0; c < 4; ++c)
                acc[r][c] += ar[r] * wlc[c] + xr[r] * wrc[c];
    }

    #pragma unroll
    for (int r = 0; r < 8; ++r) {
        int grow = row0 + ty * 8 + r;
        if (grow < n) {
            float4 o;
            o.x = acc[r][0]; o.y = acc[r][1]; o.z = acc[r][2]; o.w = acc[r][3];
            if (RELU) {
                o.x = fmaxf(o.x, 0.f); o.y = fmaxf(o.y, 0.f);
                o.z = fmaxf(o.z, 0.f); o.w = fmaxf(o.w, 0.f);
            }
            ((float4*)out)[(size_t)grow * 16 + tx] = o;
        }
    }
}

// ---------------- dot-product predictor ----------------------------------------
__global__ void k_predict(const float* __restrict__ hu, const float* __restrict__ hi,
                          const int* __restrict__ ls, const int* __restrict__ ld,
                          float* __restrict__ out)
{
    int t = blockIdx.x * blockDim.x + threadIdx.x;   // ELQ*8 exactly
    int e = t >> 3;
    int q = t & 7;
    int s = ls[e];
    int d = ld[e];
    const float4* hu4 = (const float4*)hu;
    const float4* hi4 = (const float4*)hi;
    float4 a0 = hu4[(size_t)s * 16 + q * 2];
    float4 a1 = hu4[(size_t)s * 16 + q * 2 + 1];
    float4 b0 = hi4[(size_t)d * 16 + q * 2];
    float4 b1 = hi4[(size_t)d * 16 + q * 2 + 1];
    float p = a0.x * b0.x + a0.y * b0.y + a0.z * b0.z + a0.w * b0.w
            + a1.x * b1.x + a1.y * b1.y + a1.z * b1.z + a1.w * b1.w;
    p += __shfl_down_sync(0xffffffffu, p, 4);
    p += __shfl_down_sync(0xffffffffu, p, 2);
    p += __shfl_down_sync(0xffffffffu, p, 1);
    if (q == 0) out[e] = p;
}

// ---------------- host orchestration -------------------------------------------
extern "C" void kernel_launch(void* const* d_in, const int* in_sizes, int n_in,
                              void* d_out, int out_size)
{
    const float* user_emb   = (const float*)d_in[0];
    const float* item_x     = (const float*)d_in[1];
    const float* item_lin_w = (const float*)d_in[2];
    const float* item_lin_b = (const float*)d_in[3];
    const float* Wl1_ui = (const float*)d_in[4];
    const float* Wr1_ui = (const float*)d_in[5];
    const float* b1_ui  = (const float*)d_in[6];
    const float* Wl1_iu = (const float*)d_in[7];
    const float* Wr1_iu = (const float*)d_in[8];
    const float* b1_iu  = (const float*)d_in[9];
    const float* Wl2_ui = (const float*)d_in[10];
    const float* Wr2_ui = (const float*)d_in[11];
    const float* b2_ui  = (const float*)d_in[12];
    const float* Wl2_iu = (const float*)d_in[13];
    const float* Wr2_iu = (const float*)d_in[14];
    const float* b2_iu  = (const float*)d_in[15];
    const int* user_node_id = (const int*)d_in[16];
    const int* esrc = (const int*)d_in[17];
    const int* edst = (const int*)d_in[18];
    const int* lsrc = (const int*)d_in[19];
    const int* ldst = (const int*)d_in[20];
    float* out = (float*)d_out;

    float *p_xu, *p_xi, *p_itT, *p_aggu, *p_aggi, *p_hu, *p_hi, *p_hu2, *p_hi2, *p_z;
    int *p_cntu, *p_cnti;
    cudaGetSymbolAddress((void**)&p_xu,   g_xu);
    cudaGetSymbolAddress((void**)&p_xi,   g_xi);
    cudaGetSymbolAddress((void**)&p_itT,  g_itT);
    cudaGetSymbolAddress((void**)&p_aggu, g_aggu);
    cudaGetSymbolAddress((void**)&p_aggi, g_aggi);
    cudaGetSymbolAddress((void**)&p_hu,   g_hu);
    cudaGetSymbolAddress((void**)&p_hi,   g_hi);
    cudaGetSymbolAddress((void**)&p_hu2,  g_hu2);
    cudaGetSymbolAddress((void**)&p_hi2,  g_hi2);
    cudaGetSymbolAddress((void**)&p_z,    g_zero64);
    cudaGetSymbolAddress((void**)&p_cntu, g_cntu);
    cudaGetSymbolAddress((void**)&p_cnti, g_cnti);

    const int SMEM_CI = (8192 + 64 + 2 * 64 * 68) * 4;   // 67840 B
    const int SMEM_CU = (8192 + 64 * 136) * 4;           // 67584 B
    cudaFuncSetAttribute(k_combine_i<true>,  cudaFuncAttributeMaxDynamicSharedMemorySize, SMEM_CI);
    cudaFuncSetAttribute(k_combine_i<false>, cudaFuncAttributeMaxDynamicSharedMemorySize, SMEM_CI);
    cudaFuncSetAttribute((const void*)k_combine_u<true, true>,   cudaFuncAttributeMaxDynamicSharedMemorySize, SMEM_CU);
    cudaFuncSetAttribute((const void*)k_combine_u<false, true>,  cudaFuncAttributeMaxDynamicSharedMemorySize, SMEM_CU);
    cudaFuncSetAttribute((const void*)k_combine_u<false, false>, cudaFuncAttributeMaxDynamicSharedMemorySize, SMEM_CU);

    // ---- CSR build (by src) + degrees ----
    cudaMemsetAsync(p_cntu, 0, NUQ * sizeof(int));
    cudaMemsetAsync(p_cnti, 0, NIQ * sizeof(int));
    k_hist<<<(EQ + 255) / 256, 256>>>(esrc, edst);
    k_scan1<<<NB_SCAN, 512>>>();
    k_scan2<<<1, 32>>>();
    k_scan3<<<(NUQ + 255) / 256, 256>>>();
    k_place<<<(EQ + 255) / 256, 256>>>(esrc, edst);

    // ---- input features ----
    k_gather<<<NUQ * 16 / 256, 256>>>((const float4*)user_emb, user_node_id);
    k_item_gemm<<<(NIQ + 63) / 64, 128>>>(item_x, item_lin_w, item_lin_b);

    const int GB_U = (NUQ + 127) / 128;   // user combine grid
    const int GB_I = (NIQ + 127) / 128;   // item xform grid

    // ---- layer 1 ----
    // pre-transform item table with Wl1_iu (linearity: mean then W == W then mean)
    k_combine_u<false, false><<<GB_I, 128, SMEM_CU>>>(NIQ, nullptr, nullptr,
                                                      p_xi, Wl1_iu, p_z, p_itT);
    cudaMemsetAsync(p_aggi, 0, (size_t)NIQ * DQ * sizeof(float));
    k_csr_agg<<<NUQ * 16 / 256, 256>>>((const float4*)p_xu, (const float4*)p_itT,
                                       (float4*)p_aggu, p_aggi);
    k_combine_i<true><<<(NIQ + 63) / 64, 128, SMEM_CI>>>(NIQ, p_aggi, p_cnti, p_xi,
                                                         Wl1_ui, Wr1_ui, b1_ui, p_hi);
    k_combine_u<true, true><<<GB_U, 128, SMEM_CU>>>(NUQ, p_aggu, p_cntu,
                                                    p_xu, Wr1_iu, b1_iu, p_hu);

    // ---- layer 2 ----
    k_combine_u<false, false><<<GB_I, 128, SMEM_CU>>>(NIQ, nullptr, nullptr,
                                                      p_hi, Wl2_iu, p_z, p_itT);
    cudaMemsetAsync(p_aggi, 0, (size_t)NIQ * DQ * sizeof(float));
    k_csr_agg<<<NUQ * 16 / 256, 256>>>((const float4*)p_hu, (const float4*)p_itT,
                                       (float4*)p_aggu, p_aggi);
    k_combine_i<false><<<(NIQ + 63) / 64, 128, SMEM_CI>>>(NIQ, p_aggi, p_cnti, p_hi,
                                                          Wl2_ui, Wr2_ui, b2_ui, p_hi2);
    k_combine_u<false, true><<<GB_U, 128, SMEM_CU>>>(NUQ, p_aggu, p_cntu,
                                                     p_hu, Wr2_iu, b2_iu, p_hu2);

    // ---- predictor ----
    k_predict<<<ELQ * 8 / 256, 256>>>(p_hu2, p_hi2, lsrc, ldst, out);
}

// round 6
// speedup vs baseline: 2.6630x; 1.1526x over previous
#include <cuda_runtime.h>

#define NUQ 500000
#define NIQ 100000
#define FQ  300
#define DQ  64
#define EQ  2000000
#define ELQ 1000000
#define NB_SCAN 123            // ceil(NUQ / 4096)
#define UPB 64                 // users per block in fused user layer

// ---------------- scratch (device globals; no allocations allowed) -------------
__device__ __align__(16) float g_xi  [NIQ * DQ];   // item input features
__device__ __align__(16) float g_itT [NIQ * DQ];   // transformed item table (x_i @ Wl_iu)
__device__ __align__(16) float g_aggi[NIQ * DQ];   // item aggregate of raw user rows
__device__ __align__(16) float g_hu  [NUQ * DQ];
__device__ __align__(16) float g_hi  [NIQ * DQ];
__device__ __align__(16) float g_hu2 [NUQ * DQ];
__device__ __align__(16) float g_hi2 [NIQ * DQ];
__device__ float g_zero64[DQ];                     // stays zero (zero-initialized)

// CSR-by-src machinery
__device__ int g_cntu  [NUQ];
__device__ int g_cnti  [NIQ];
__device__ int g_pre   [NUQ];
__device__ int g_rowptr[NUQ];
__device__ int g_cursor[NUQ];
__device__ int g_bsum  [128];
__device__ int g_boff  [128];
__device__ int g_dsts  [EQ];

// ---------------- histogram ----------------------------------------------------
__global__ void k_hist(const int* __restrict__ src, const int* __restrict__ dst) {
    int i = blockIdx.x * blockDim.x + threadIdx.x;
    if (i < EQ) {
        atomicAdd(&g_cntu[src[i]], 1);
        atomicAdd(&g_cnti[dst[i]], 1);
    }
}

// ---------------- hierarchical exclusive scan of g_cntu ------------------------
__global__ __launch_bounds__(512) void k_scan1() {
    __shared__ int swarp[16];
    const int t = threadIdx.x;
    const int base = blockIdx.x * 4096 + t * 8;
    int v[8], s = 0;
    #pragma unroll
    for (int j = 0; j < 8; ++j) {
        v[j] = (base + j < NUQ) ? g_cntu[base + j] : 0;
        s += v[j];
    }
    const int lane = t & 31, w = t >> 5;
    int x = s;
    #pragma unroll
    for (int off = 1; off < 32; off <<= 1) {
        int y = __shfl_up_sync(0xffffffffu, x, off);
        if (lane >= off) x += y;
    }
    if (lane == 31) swarp[w] = x;
    __syncthreads();
    if (w == 0) {
        int y = (lane < 16) ? swarp[lane] : 0;
        #pragma unroll
        for (int off = 1; off < 16; off <<= 1) {
            int z = __shfl_up_sync(0xffffffffu, y, off);
            if (lane >= off) y += z;
        }
        if (lane < 16) swarp[lane] = y;
    }
    __syncthreads();
    int run = (w > 0 ? swarp[w - 1] : 0) + (x - s);
    #pragma unroll
    for (int j = 0; j < 8; ++j) {
        if (base + j < NUQ) g_pre[base + j] = run;
        run += v[j];
    }
    if (t == 0) g_bsum[blockIdx.x] = swarp[15];
}

__global__ void k_scan2() {
    if (threadIdx.x == 0 && blockIdx.x == 0) {
        int a = 0;
        for (int i = 0; i < NB_SCAN; ++i) { g_boff[i] = a; a += g_bsum[i]; }
    }
}

__global__ void k_scan3() {
    int i = blockIdx.x * blockDim.x + threadIdx.x;
    if (i < NUQ) {
        int r = g_pre[i] + g_boff[i >> 12];
        g_rowptr[i] = r;
        g_cursor[i] = r;
    }
}

__global__ void k_place(const int* __restrict__ src, const int* __restrict__ dst) {
    int i = blockIdx.x * blockDim.x + threadIdx.x;
    if (i < EQ) {
        int s = src[i];
        int pos = atomicAdd(&g_cursor[s], 1);
        g_dsts[pos] = dst[i];
    }
}

// ---------------- item linear GEMM: xi = item_x @ W + b ------------------------
__global__ __launch_bounds__(128) void k_item_gemm(
    const float* __restrict__ X, const float* __restrict__ W, const float* __restrict__ bias)
{
    __shared__ float sW [60 * 64];
    __shared__ float sXT[60 * 68];

    const int tid = threadIdx.x;
    const int tx  = tid & 15;
    const int ty  = tid >> 4;
    const int row0 = blockIdx.x * 64;

    const float4 bv = ((const float4*)bias)[tx];
    float acc[8][4];
    #pragma unroll
    for (int r = 0; r < 8; ++r) {
        acc[r][0] = bv.x; acc[r][1] = bv.y; acc[r][2] = bv.z; acc[r][3] = bv.w;
    }

    for (int k0 = 0; k0 < FQ; k0 += 60) {
        __syncthreads();
        const float4* Wg = (const float4*)(W + k0 * 64);
        for (int i = tid; i < 960; i += 128)
            ((float4*)sW)[i] = Wg[i];
        for (int i = tid; i < 960; i += 128) {
            int r  = i / 15;
            int c4 = i - r * 15;
            int grow = row0 + r;
            float4 v = make_float4(0.f, 0.f, 0.f, 0.f);
            if (grow < NIQ)
                v = *(const float4*)(X + (size_t)grow * FQ + k0 + c4 * 4);
            int k = c4 * 4;
            sXT[(k + 0) * 68 + r] = v.x;
            sXT[(k + 1) * 68 + r] = v.y;
            sXT[(k + 2) * 68 + r] = v.z;
            sXT[(k + 3) * 68 + r] = v.w;
        }
        __syncthreads();

        #pragma unroll 6
        for (int k = 0; k < 60; ++k) {
            float4 a0 = *(const float4*)&sXT[k * 68 + ty * 8];
            float4 a1 = *(const float4*)&sXT[k * 68 + ty * 8 + 4];
            float4 w  = *(const float4*)&sW [k * 64 + tx * 4];
            float ar[8] = {a0.x, a0.y, a0.z, a0.w, a1.x, a1.y, a1.z, a1.w};
            #pragma unroll
            for (int r = 0; r < 8; ++r) {
                acc[r][0] += ar[r] * w.x;
                acc[r][1] += ar[r] * w.y;
                acc[r][2] += ar[r] * w.z;
                acc[r][3] += ar[r] * w.w;
            }
        }
    }

    #pragma unroll
    for (int r = 0; r < 8; ++r) {
        int grow = row0 + ty * 8 + r;
        if (grow < NIQ) {
            float4 o = make_float4(acc[r][0], acc[r][1], acc[r][2], acc[r][3]);
            ((float4*)g_xi)[(size_t)grow * 16 + tx] = o;
        }
    }
}

// ---------------- f32x2 item transform: itT = x @ W (no bias) -------------------
// 128 rows x 64 cols per block, 128 threads; row-pair packed f32x2.
__global__ __launch_bounds__(128) void k_xform(
    int n, const float* __restrict__ x, const float* __restrict__ W,
    float* __restrict__ out)
{
    extern __shared__ float sm[];
    double* sWd = (double*)sm;        // 4096 doubles (W duplicated) = 32 KB
    float*  saT = sm + 8192;          // 64 x 136 floats (x transposed)

    const int tid = threadIdx.x;
    const int tx = tid & 7;
    const int ty = tid >> 3;
    const int row0 = blockIdx.x * 128;

    for (int i = tid; i < 4096; i += 128) {
        unsigned int wb = __float_as_uint(W[i]);
        unsigned long long wd = ((unsigned long long)wb << 32) | wb;
        sWd[i] = __longlong_as_double(wd);
    }
    for (int i = tid; i < 2048; i += 128) {
        int r = i >> 4, c4 = i & 15;
        int grow = row0 + r;
        float4 v = make_float4(0.f, 0.f, 0.f, 0.f);
        if (grow < n) v = ((const float4*)x)[(size_t)grow * 16 + c4];
        int k = c4 * 4;
        saT[(k + 0) * 136 + r] = v.x;
        saT[(k + 1) * 136 + r] = v.y;
        saT[(k + 2) * 136 + r] = v.z;
        saT[(k + 3) * 136 + r] = v.w;
    }
    __syncthreads();

    unsigned long long acc[4][8];
    #pragma unroll
    for (int ci = 0; ci < 8; ++ci)
        #pragma unroll
        for (int j = 0; j < 4; ++j) acc[j][ci] = 0ull;

    #pragma unroll 4
    for (int k = 0; k < 64; ++k) {
        unsigned long long ap[4];
        const double* arow = (const double*)(saT + k * 136 + ty * 8);
        #pragma unroll
        for (int j = 0; j < 4; ++j) ap[j] = __double_as_longlong(arow[j]);
        #pragma unroll
        for (int ci = 0; ci < 8; ++ci) {
            unsigned long long wd = __double_as_longlong(sWd[k * 64 + tx + 8 * ci]);
            #pragma unroll
            for (int j = 0; j < 4; ++j)
                asm("fma.rn.f32x2 %0, %1, %2, %0;" : "+l"(acc[j][ci]) : "l"(ap[j]), "l"(wd));
        }
    }

    #pragma unroll
    for (int j = 0; j < 4; ++j) {
        int r0 = row0 + ty * 8 + 2 * j;
        int r1 = r0 + 1;
        #pragma unroll
        for (int ci = 0; ci < 8; ++ci) {
            int c = tx + 8 * ci;
            float lo = __uint_as_float((unsigned int)(acc[j][ci] & 0xffffffffull));
            float hi = __uint_as_float((unsigned int)(acc[j][ci] >> 32));
            if (r0 < n) out[(size_t)r0 * 64 + c] = lo;
            if (r1 < n) out[(size_t)r1 * 64 + c] = hi;
        }
    }
}

// ---------------- fused user layer ---------------------------------------------
// Phase A: half-warp per user (4 users each): load raw user row (emb[nid[u]] for
// layer 1, hu for layer 2), CSR edge loop: acc += itT[d] (transformed items),
// RED raw row into aggi. Stage mean + raw row in smem.
// Phase B: block GEMM out = act(mean + xrow @ W + b), k-pair packed f32x2.
__device__ __forceinline__ void red_add_v4(float* p, float4 v) {
    asm volatile("red.global.add.v4.f32 [%0], {%1, %2, %3, %4};"
                 :: "l"(p), "f"(v.x), "f"(v.y), "f"(v.z), "f"(v.w) : "memory");
}

template <bool RELU, bool L1>
__global__ __launch_bounds__(256) void k_user_layer(
    const float4* __restrict__ usrc, const int* __restrict__ nid,
    const float4* __restrict__ itabT, float* __restrict__ aggi,
    const float* __restrict__ W, const float* __restrict__ b,
    float* __restrict__ outp)
{
    extern __shared__ float sm[];
    double* sWp   = (double*)sm;           // 2048 doubles: k-pair packed W (16 KB)
    float*  sx    = sm + 4096;             // UPB x 68 raw user rows (pitch 68)
    float*  smean = sx + UPB * 68;         // UPB x 64 mean aggregates

    const int tid = threadIdx.x;

    // stage W as k-pair doubles: sWp[kp*64 + c] = (W[2kp][c], W[2kp+1][c])
    for (int idx = tid; idx < 2048; idx += 256) {
        int kp = idx >> 6, c = idx & 63;
        unsigned int lo = __float_as_uint(W[kp * 128 + c]);
        unsigned int hi = __float_as_uint(W[kp * 128 + 64 + c]);
        sWp[idx] = __longlong_as_double(((unsigned long long)hi << 32) | lo);
    }

    // ---- phase A ----
    const int h = tid >> 4;     // half-warp id 0..15
    const int q = tid & 15;
    #pragma unroll
    for (int i = 0; i < 4; ++i) {
        int r = h * 4 + i;
        int u = blockIdx.x * UPB + r;
        float4 xr  = make_float4(0.f, 0.f, 0.f, 0.f);
        float4 acc = make_float4(0.f, 0.f, 0.f, 0.f);
        float rd = 0.f;
        if (u < NUQ) {
            int row = L1 ? __ldg(&nid[u]) : u;
            xr = usrc[(size_t)row * 16 + q];
            int beg = __ldg(&g_rowptr[u]);
            int cnt = __ldg(&g_cntu[u]);
            for (int e = beg; e < beg + cnt; ++e) {
                int d = __ldg(&g_dsts[e]);
                float4 iv = itabT[(size_t)d * 16 + q];
                acc.x += iv.x; acc.y += iv.y; acc.z += iv.z; acc.w += iv.w;
                red_add_v4(aggi + (size_t)d * 64 + q * 4, xr);
            }
            rd = 1.f / fmaxf((float)cnt, 1.f);
        }
        *(float4*)&smean[r * 64 + q * 4] = make_float4(acc.x * rd, acc.y * rd,
                                                       acc.z * rd, acc.w * rd);
        *(float4*)&sx[r * 68 + q * 4] = xr;
    }
    __syncthreads();

    // ---- phase B: GEMM 64x64x64, k-pair f32x2 ----
    const int cg = tid & 15, rg = tid >> 4;
    const int c0 = cg * 4, r0 = rg * 4;

    unsigned long long acc2[4][4];
    #pragma unroll
    for (int j = 0; j < 4; ++j)
        #pragma unroll
        for (int c = 0; c < 4; ++c) acc2[j][c] = 0ull;

    #pragma unroll 8
    for (int kp = 0; kp < 32; ++kp) {
        unsigned long long a2[4];
        #pragma unroll
        for (int j = 0; j < 4; ++j)
            a2[j] = __double_as_longlong(*(const double*)&sx[(r0 + j) * 68 + 2 * kp]);
        double2 w01 = *(const double2*)&sWp[kp * 64 + c0];
        double2 w23 = *(const double2*)&sWp[kp * 64 + c0 + 2];
        unsigned long long w2[4] = {
            __double_as_longlong(w01.x), __double_as_longlong(w01.y),
            __double_as_longlong(w23.x), __double_as_longlong(w23.y)
        };
        #pragma unroll
        for (int j = 0; j < 4; ++j)
            #pragma unroll
            for (int c = 0; c < 4; ++c)
                asm("fma.rn.f32x2 %0, %1, %2, %0;" : "+l"(acc2[j][c]) : "l"(a2[j]), "l"(w2[c]));
    }

    const float4 bv = *(const float4*)(b + c0);
    #pragma unroll
    for (int j = 0; j < 4; ++j) {
        int u = blockIdx.x * UPB + r0 + j;
        if (u < NUQ) {
            float4 m = *(const float4*)&smean[(r0 + j) * 64 + c0];
            float o0 = __uint_as_float((unsigned int)(acc2[j][0] & 0xffffffffull))
                     + __uint_as_float((unsigned int)(acc2[j][0] >> 32)) + m.x + bv.x;
            float o1 = __uint_as_float((unsigned int)(acc2[j][1] & 0xffffffffull))
                     + __uint_as_float((unsigned int)(acc2[j][1] >> 32)) + m.y + bv.y;
            float o2 = __uint_as_float((unsigned int)(acc2[j][2] & 0xffffffffull))
                     + __uint_as_float((unsigned int)(acc2[j][2] >> 32)) + m.z + bv.z;
            float o3 = __uint_as_float((unsigned int)(acc2[j][3] & 0xffffffffull))
                     + __uint_as_float((unsigned int)(acc2[j][3] >> 32)) + m.w + bv.w;
            if (RELU) {
                o0 = fmaxf(o0, 0.f); o1 = fmaxf(o1, 0.f);
                o2 = fmaxf(o2, 0.f); o3 = fmaxf(o3, 0.f);
            }
            *(float4*)&outp[(size_t)u * 64 + c0] = make_float4(o0, o1, o2, o3);
        }
    }
}

// ---------------- dual GEMM combine (item side, 100k rows) ---------------------
template <bool RELU>
__global__ __launch_bounds__(128) void k_combine_i(
    int n, const float* __restrict__ agg, const int* __restrict__ deg,
    const float* __restrict__ x, const float* __restrict__ Wl,
    const float* __restrict__ Wr, const float* __restrict__ b,
    float* __restrict__ out)
{
    extern __shared__ float sm[];
    float* sWl = sm;
    float* sWr = sm + 4096;
    float* sB  = sm + 8192;
    float* saT = sm + 8192 + 64;
    float* sxT = saT + 64 * 68;

    const int tid = threadIdx.x;
    const int tx = tid & 15;
    const int ty = tid >> 4;
    const int row0 = blockIdx.x * 64;

    for (int i = tid; i < 4096; i += 128) { sWl[i] = Wl[i]; sWr[i] = Wr[i]; }
    if (tid < 64) sB[tid] = b[tid];

    for (int i = tid; i < 1024; i += 128) {
        int r = i >> 4, c4 = i & 15;
        int grow = row0 + r;
        float4 av, xv;
        float rd = 1.f;
        if (grow < n) {
            av = ((const float4*)agg)[(size_t)grow * 16 + c4];
            xv = ((const float4*)x)[(size_t)grow * 16 + c4];
            rd = 1.f / fmaxf((float)deg[grow], 1.f);
        } else {
            av = make_float4(0.f, 0.f, 0.f, 0.f);
            xv = av;
        }
        int c = c4 * 4;
        saT[(c + 0) * 68 + r] = av.x * rd;
        saT[(c + 1) * 68 + r] = av.y * rd;
        saT[(c + 2) * 68 + r] = av.z * rd;
        saT[(c + 3) * 68 + r] = av.w * rd;
        sxT[(c + 0) * 68 + r] = xv.x;
        sxT[(c + 1) * 68 + r] = xv.y;
        sxT[(c + 2) * 68 + r] = xv.z;
        sxT[(c + 3) * 68 + r] = xv.w;
    }
    __syncthreads();

    float acc[8][4];
    {
        float4 bv = *(const float4*)&sB[tx * 4];
        #pragma unroll
        for (int r = 0; r < 8; ++r) {
            acc[r][0] = bv.x; acc[r][1] = bv.y; acc[r][2] = bv.z; acc[r][3] = bv.w;
        }
    }

    #pragma unroll 4
    for (int k = 0; k < 64; ++k) {
        float4 a0 = *(const float4*)&saT[k * 68 + ty * 8];
        float4 a1 = *(const float4*)&saT[k * 68 + ty * 8 + 4];
        float4 wl = *(const float4*)&sWl[k * 64 + tx * 4];
        float4 x0 = *(const float4*)&sxT[k * 68 + ty * 8];
        float4 x1 = *(const float4*)&sxT[k * 68 + ty * 8 + 4];
        float4 wr = *(const float4*)&sWr[k * 64 + tx * 4];

        float ar[8] = {a0.x, a0.y, a0.z, a0.w, a1.x, a1.y, a1.z, a1.w};
        float xr[8] = {x0.x, x0.y, x0.z, x0.w, x1.x, x1.y, x1.z, x1.w};
        float wlc[4] = {wl.x, wl.y, wl.z, wl.w};
        float wrc[4] = {wr.x, wr.y, wr.z, wr.w};
        #pragma unroll
        for (int r = 0; r < 8; ++r)
            #pragma unroll
            for (int c = 0; c < 4; ++c)
                acc[r][c] += ar[r] * wlc[c] + xr[r] * wrc[c];
    }

    #pragma unroll
    for (int r = 0; r < 8; ++r) {
        int grow = row0 + ty * 8 + r;
        if (grow < n) {
            float4 o;
            o.x = acc[r][0]; o.y = acc[r][1]; o.z = acc[r][2]; o.w = acc[r][3];
            if (RELU) {
                o.x = fmaxf(o.x, 0.f); o.y = fmaxf(o.y, 0.f);
                o.z = fmaxf(o.z, 0.f); o.w = fmaxf(o.w, 0.f);
            }
            ((float4*)out)[(size_t)grow * 16 + tx] = o;
        }
    }
}

// ---------------- dot-product predictor ----------------------------------------
__global__ void k_predict(const float* __restrict__ hu, const float* __restrict__ hi,
                          const int* __restrict__ ls, const int* __restrict__ ld,
                          float* __restrict__ out)
{
    int t = blockIdx.x * blockDim.x + threadIdx.x;   // ELQ*8 exactly
    int e = t >> 3;
    int q = t & 7;
    int s = ls[e];
    int d = ld[e];
    const float4* hu4 = (const float4*)hu;
    const float4* hi4 = (const float4*)hi;
    float4 a0 = hu4[(size_t)s * 16 + q * 2];
    float4 a1 = hu4[(size_t)s * 16 + q * 2 + 1];
    float4 b0 = hi4[(size_t)d * 16 + q * 2];
    float4 b1 = hi4[(size_t)d * 16 + q * 2 + 1];
    float p = a0.x * b0.x + a0.y * b0.y + a0.z * b0.z + a0.w * b0.w
            + a1.x * b1.x + a1.y * b1.y + a1.z * b1.z + a1.w * b1.w;
    p += __shfl_down_sync(0xffffffffu, p, 4);
    p += __shfl_down_sync(0xffffffffu, p, 2);
    p += __shfl_down_sync(0xffffffffu, p, 1);
    if (q == 0) out[e] = p;
}

// ---------------- host orchestration -------------------------------------------
extern "C" void kernel_launch(void* const* d_in, const int* in_sizes, int n_in,
                              void* d_out, int out_size)
{
    const float* user_emb   = (const float*)d_in[0];
    const float* item_x     = (const float*)d_in[1];
    const float* item_lin_w = (const float*)d_in[2];
    const float* item_lin_b = (const float*)d_in[3];
    const float* Wl1_ui = (const float*)d_in[4];
    const float* Wr1_ui = (const float*)d_in[5];
    const float* b1_ui  = (const float*)d_in[6];
    const float* Wl1_iu = (const float*)d_in[7];
    const float* Wr1_iu = (const float*)d_in[8];
    const float* b1_iu  = (const float*)d_in[9];
    const float* Wl2_ui = (const float*)d_in[10];
    const float* Wr2_ui = (const float*)d_in[11];
    const float* b2_ui  = (const float*)d_in[12];
    const float* Wl2_iu = (const float*)d_in[13];
    const float* Wr2_iu = (const float*)d_in[14];
    const float* b2_iu  = (const float*)d_in[15];
    const int* user_node_id = (const int*)d_in[16];
    const int* esrc = (const int*)d_in[17];
    const int* edst = (const int*)d_in[18];
    const int* lsrc = (const int*)d_in[19];
    const int* ldst = (const int*)d_in[20];
    float* out = (float*)d_out;

    float *p_xi, *p_itT, *p_aggi, *p_hu, *p_hi, *p_hu2, *p_hi2;
    int *p_cntu, *p_cnti;
    cudaGetSymbolAddress((void**)&p_xi,   g_xi);
    cudaGetSymbolAddress((void**)&p_itT,  g_itT);
    cudaGetSymbolAddress((void**)&p_aggi, g_aggi);
    cudaGetSymbolAddress((void**)&p_hu,   g_hu);
    cudaGetSymbolAddress((void**)&p_hi,   g_hi);
    cudaGetSymbolAddress((void**)&p_hu2,  g_hu2);
    cudaGetSymbolAddress((void**)&p_hi2,  g_hi2);
    cudaGetSymbolAddress((void**)&p_cntu, g_cntu);
    cudaGetSymbolAddress((void**)&p_cnti, g_cnti);

    const int SMEM_CI = (8192 + 64 + 2 * 64 * 68) * 4;          // 67840 B
    const int SMEM_XF = (8192 + 64 * 136) * 4;                  // 67584 B
    const int SMEM_UL = 2048 * 8 + (UPB * 68 + UPB * 64) * 4;   // 50176 B
    cudaFuncSetAttribute(k_combine_i<true>,  cudaFuncAttributeMaxDynamicSharedMemorySize, SMEM_CI);
    cudaFuncSetAttribute(k_combine_i<false>, cudaFuncAttributeMaxDynamicSharedMemorySize, SMEM_CI);
    cudaFuncSetAttribute(k_xform,            cudaFuncAttributeMaxDynamicSharedMemorySize, SMEM_XF);
    cudaFuncSetAttribute((const void*)k_user_layer<true, true>,   cudaFuncAttributeMaxDynamicSharedMemorySize, SMEM_UL);
    cudaFuncSetAttribute((const void*)k_user_layer<false, false>, cudaFuncAttributeMaxDynamicSharedMemorySize, SMEM_UL);

    // ---- CSR build (by src) + degrees ----
    cudaMemsetAsync(p_cntu, 0, NUQ * sizeof(int));
    cudaMemsetAsync(p_cnti, 0, NIQ * sizeof(int));
    k_hist<<<(EQ + 255) / 256, 256>>>(esrc, edst);
    k_scan1<<<NB_SCAN, 512>>>();
    k_scan2<<<1, 32>>>();
    k_scan3<<<(NUQ + 255) / 256, 256>>>();
    k_place<<<(EQ + 255) / 256, 256>>>(esrc, edst);

    // ---- item input features ----
    k_item_gemm<<<(NIQ + 63) / 64, 128>>>(item_x, item_lin_w, item_lin_b);

    const int GB_UL = (NUQ + UPB - 1) / UPB;
    const int GB_XF = (NIQ + 127) / 128;

    // ---- layer 1 ----
    k_xform<<<GB_XF, 128, SMEM_XF>>>(NIQ, p_xi, Wl1_iu, p_itT);
    cudaMemsetAsync(p_aggi, 0, (size_t)NIQ * DQ * sizeof(float));
    k_user_layer<true, true><<<GB_UL, 256, SMEM_UL>>>(
        (const float4*)user_emb, user_node_id, (const float4*)p_itT, p_aggi,
        Wr1_iu, b1_iu, p_hu);
    k_combine_i<true><<<(NIQ + 63) / 64, 128, SMEM_CI>>>(NIQ, p_aggi, p_cnti, p_xi,
                                                         Wl1_ui, Wr1_ui, b1_ui, p_hi);

    // ---- layer 2 ----
    k_xform<<<GB_XF, 128, SMEM_XF>>>(NIQ, p_hi, Wl2_iu, p_itT);
    cudaMemsetAsync(p_aggi, 0, (size_t)NIQ * DQ * sizeof(float));
    k_user_layer<false, false><<<GB_UL, 256, SMEM_UL>>>(
        (const float4*)p_hu, nullptr, (const float4*)p_itT, p_aggi,
        Wr2_iu, b2_iu, p_hu2);
    k_combine_i<false><<<(NIQ + 63) / 64, 128, SMEM_CI>>>(NIQ, p_aggi, p_cnti, p_hi,
                                                          Wl2_ui, Wr2_ui, b2_ui, p_hi2);

    // ---- predictor ----
    k_predict<<<ELQ * 8 / 256, 256>>>(p_hu2, p_hi2, lsrc, ldst, out);
}